// round 1
// baseline (speedup 1.0000x reference)
#include <cuda_runtime.h>
#include <math.h>

#define Bz   2
#define Cd   256
#define Hh   40
#define Wd   40
#define HW   1600
#define TOK  3200          // Bz*HW
#define NHd  8
#define HDd  32
#define WSd  15
#define W2Sd 225
#define MDd  7
#define HIDd 1024
#define GNg  32
#define EPSf 1e-5f
#define NEGINF -1e38f

// ---------------- scratch (device globals; no allocation) ----------------
__device__ float g_qln[TOK*Cd];
__device__ float g_kln[TOK*Cd];
__device__ float g_vln[TOK*Cd];
__device__ float g_Q[TOK*Cd];
__device__ float g_K[TOK*Cd];
__device__ float g_V[TOK*Cd];
__device__ float g_att[TOK*Cd];
__device__ float g_tmp[TOK*Cd];    // proj out / mlp out
__device__ float g_x1[TOK*Cd];     // residual after attention
__device__ float g_ln2[TOK*Cd];
__device__ float g_h1[TOK*HIDd];
__device__ float g_ga[TOK*HIDd];
__device__ float g_cv[TOK*HIDd];
__device__ float g_gnm[Bz*GNg*2];  // mean, rstd per (b, group)

// ---------------- fused LN of img / img_warp / img_warp+mask ----------------
__global__ void ln3_kernel(const float* __restrict__ img,
                           const float* __restrict__ imw,
                           const float* __restrict__ msk,
                           const float* __restrict__ g1,
                           const float* __restrict__ b1) {
    int tok = blockIdx.x;
    int c   = threadIdx.x;
    int b   = tok / HW, pos = tok % HW;
    int off = (b*Cd + c)*HW + pos;

    float x0 = img[off];
    float x1 = imw[off];
    float x2 = x1 + msk[off];
    float gg = g1[c], bb = b1[c];

    __shared__ float ssum[256];
    __shared__ float ssq[256];

    float vals[3] = {x0, x1, x2};
    float* outs[3] = {g_qln, g_kln, g_vln};

    for (int r = 0; r < 3; r++) {
        float v = vals[r];
        ssum[c] = v; ssq[c] = v*v;
        __syncthreads();
        for (int st = 128; st > 0; st >>= 1) {
            if (c < st) { ssum[c] += ssum[c+st]; ssq[c] += ssq[c+st]; }
            __syncthreads();
        }
        float mu  = ssum[0] * (1.0f/Cd);
        float var = ssq[0]  * (1.0f/Cd) - mu*mu;
        __syncthreads();
        outs[r][tok*Cd + c] = (v - mu) * rsqrtf(var + EPSf) * gg + bb;
    }
}

// ---------------- LN on token-major buffer ----------------
__global__ void ln_tok_kernel(const float* __restrict__ g1,
                              const float* __restrict__ b1) {
    int tok = blockIdx.x;
    int c   = threadIdx.x;
    float v = g_x1[tok*Cd + c];

    __shared__ float ssum[256];
    __shared__ float ssq[256];
    ssum[c] = v; ssq[c] = v*v;
    __syncthreads();
    for (int st = 128; st > 0; st >>= 1) {
        if (c < st) { ssum[c] += ssum[c+st]; ssq[c] += ssq[c+st]; }
        __syncthreads();
    }
    float mu  = ssum[0] * (1.0f/Cd);
    float var = ssq[0]  * (1.0f/Cd) - mu*mu;
    g_ln2[tok*Cd + c] = (v - mu) * rsqrtf(var + EPSf) * g1[c] + b1[c];
}

// ---------------- tiled fp32 GEMM: C[M,N] = A[M,K] * W[N,K]^T + bias[N] -------
// BM=BN=64, BK=16, 256 threads, 4x4 per thread. M,N %64==0, K %16==0.
__global__ void gemm_kernel(const float* __restrict__ A,
                            const float* __restrict__ W,
                            const float* __restrict__ bias,
                            float* __restrict__ C,
                            int M, int N, int K) {
    __shared__ float As[16][65];
    __shared__ float Ws[16][65];
    int n0 = blockIdx.x * 64;
    int m0 = blockIdx.y * 64;
    int tid = threadIdx.x;
    int tx = tid & 15, ty = tid >> 4;

    float acc[4][4] = {};

    for (int k0 = 0; k0 < K; k0 += 16) {
        #pragma unroll
        for (int i = 0; i < 4; i++) {
            int l = tid + i*256;
            int m = l >> 4, k = l & 15;
            As[k][m] = A[(m0+m)*K + k0 + k];
            Ws[k][m] = W[(n0+m)*K + k0 + k];
        }
        __syncthreads();
        #pragma unroll
        for (int k = 0; k < 16; k++) {
            float ra[4], rb[4];
            #pragma unroll
            for (int i = 0; i < 4; i++) ra[i] = As[k][ty*4+i];
            #pragma unroll
            for (int j = 0; j < 4; j++) rb[j] = Ws[k][tx*4+j];
            #pragma unroll
            for (int i = 0; i < 4; i++)
                #pragma unroll
                for (int j = 0; j < 4; j++)
                    acc[i][j] += ra[i]*rb[j];
        }
        __syncthreads();
    }

    #pragma unroll
    for (int i = 0; i < 4; i++) {
        #pragma unroll
        for (int j = 0; j < 4; j++) {
            int n = n0 + tx*4 + j;
            C[(m0+ty*4+i)*N + n] = acc[i][j] + bias[n];
        }
    }
}

// ---------------- local windowed attention with q-conditioned rel bias -------
__global__ void attn_kernel(const float* __restrict__ Wrel,
                            const float* __restrict__ brel) {
    int tok = blockIdx.x;
    int h   = blockIdx.y;
    int b   = tok / HW, pos = tok % HW;
    int y   = pos / Wd, x = pos % Wd;
    int t   = threadIdx.x;

    __shared__ float qs[HDd];
    __shared__ float sc[W2Sd];
    __shared__ float red[256];

    if (t < HDd) qs[t] = g_Q[tok*Cd + h*HDd + t];
    __syncthreads();

    float s = NEGINF;
    if (t < W2Sd) {
        int oy = t / WSd, ox = t - oy*WSd;
        int ky = y + oy - MDd, kx = x + ox - MDd;
        if (ky >= 0 && ky < Hh && kx >= 0 && kx < Wd) {
            float rel = brel[h*W2Sd + t];
            const float* wr = Wrel + (h*W2Sd + t)*HDd;
            const float* kp = g_K + (size_t)(b*HW + ky*Wd + kx)*Cd + h*HDd;
            float d = 0.f;
            #pragma unroll
            for (int c = 0; c < HDd; c++) {
                rel += wr[c]*qs[c];
                d   += qs[c]*kp[c];
            }
            s = d * 0.17677669529663687f + rel;
        }
    }

    red[t] = s;
    __syncthreads();
    for (int st = 128; st > 0; st >>= 1) {
        if (t < st) red[t] = fmaxf(red[t], red[t+st]);
        __syncthreads();
    }
    float mx = red[0];
    __syncthreads();

    float e = (t < W2Sd && s > -1e37f) ? __expf(s - mx) : 0.f;
    if (t < W2Sd) sc[t] = e;
    red[t] = e;
    __syncthreads();
    for (int st = 128; st > 0; st >>= 1) {
        if (t < st) red[t] += red[t+st];
        __syncthreads();
    }
    float inv = 1.f / red[0];
    __syncthreads();

    // weighted V sum: c = t&31, partial group g = t>>5 over offsets
    int c = t & 31, g = t >> 5;
    float acc = 0.f;
    for (int o = g; o < W2Sd; o += 8) {
        int oy = o / WSd, ox = o - oy*WSd;
        int ky = y + oy - MDd, kx = x + ox - MDd;
        if (ky >= 0 && ky < Hh && kx >= 0 && kx < Wd)
            acc += sc[o] * g_V[(size_t)(b*HW + ky*Wd + kx)*Cd + h*HDd + c];
    }
    red[t] = acc;
    __syncthreads();
    if (t < HDd) {
        float tot = 0.f;
        #pragma unroll
        for (int g2 = 0; g2 < 8; g2++) tot += red[g2*32 + t];
        g_att[tok*Cd + h*HDd + t] = tot * inv;
    }
}

// ---------------- residual: x1 = proj_out + img tokens ----------------
__global__ void addres_kernel(const float* __restrict__ img) {
    int idx = blockIdx.x*256 + threadIdx.x;
    int tok = idx / Cd, c = idx % Cd;
    int b = tok / HW, pos = tok % HW;
    g_x1[idx] = g_tmp[idx] + img[(b*Cd + c)*HW + pos];
}

// ---------------- GroupNorm stats per (b, group) ----------------
__global__ void gn_stats_kernel() {
    int bg = blockIdx.x;
    int b = bg / GNg, g = bg % GNg;
    int tid = threadIdx.x;
    float sm = 0.f, sq = 0.f;
    for (int i = tid; i < HW*32; i += 256) {
        int ch  = g*32 + (i & 31);
        int pos = i >> 5;
        float v = g_h1[(size_t)(b*HW + pos)*HIDd + ch];
        sm += v; sq += v*v;
    }
    __shared__ float s1[256], s2[256];
    s1[tid] = sm; s2[tid] = sq;
    __syncthreads();
    for (int st = 128; st > 0; st >>= 1) {
        if (tid < st) { s1[tid] += s1[tid+st]; s2[tid] += s2[tid+st]; }
        __syncthreads();
    }
    if (tid == 0) {
        float cnt = (float)(HW*32);
        float mu  = s1[0] / cnt;
        float var = s2[0] / cnt - mu*mu;
        g_gnm[bg*2]   = mu;
        g_gnm[bg*2+1] = rsqrtf(var + EPSf);
    }
}

// ---------------- GN normalize + exact GELU ----------------
__global__ void gn_gelu_kernel(const float* __restrict__ gg,
                               const float* __restrict__ gb) {
    int idx = blockIdx.x*256 + threadIdx.x;
    int ch  = idx % HIDd;
    int tok = idx / HIDd;
    int b   = tok / HW;
    int grp = ch >> 5;
    float mu = g_gnm[(b*GNg + grp)*2];
    float rs = g_gnm[(b*GNg + grp)*2 + 1];
    float v  = (g_h1[idx] - mu) * rs * gg[ch] + gb[ch];
    g_ga[idx] = 0.5f * v * (1.f + erff(v * 0.70710678118654752f));
}

// ---------------- 5x5 depthwise conv, pad 2, no bias ----------------
__global__ void dwconv_kernel(const float* __restrict__ Wdw) {
    int idx = blockIdx.x*256 + threadIdx.x;
    int ch  = idx % HIDd;
    int tok = idx / HIDd;
    int b   = tok / HW, pos = tok % HW;
    int y   = pos / Wd, x = pos % Wd;
    float acc = 0.f;
    #pragma unroll
    for (int dy = 0; dy < 5; dy++) {
        int yy = y + dy - 2;
        if (yy < 0 || yy >= Hh) continue;
        #pragma unroll
        for (int dx = 0; dx < 5; dx++) {
            int xx = x + dx - 2;
            if (xx < 0 || xx >= Wd) continue;
            acc += Wdw[ch*25 + dy*5 + dx] *
                   g_ga[(size_t)(b*HW + yy*Wd + xx)*HIDd + ch];
        }
    }
    g_cv[idx] = acc;
}

// ---------------- final: out[BCHW] = x1 + mlp_out ----------------
__global__ void final_kernel(float* __restrict__ out) {
    int idx = blockIdx.x*256 + threadIdx.x;   // BCHW index
    int pos = idx % HW;
    int bc  = idx / HW;
    int c   = bc % Cd, b = bc / Cd;
    int t   = (b*HW + pos)*Cd + c;
    out[idx] = g_x1[t] + g_tmp[t];
}

// ---------------- launch ----------------
extern "C" void kernel_launch(void* const* d_in, const int* in_sizes, int n_in,
                              void* d_out, int out_size) {
    const float* img   = (const float*)d_in[0];
    const float* imw   = (const float*)d_in[1];
    const float* msk   = (const float*)d_in[2];
    const float* ln1g  = (const float*)d_in[3];
    const float* ln1b  = (const float*)d_in[4];
    const float* ln2g  = (const float*)d_in[5];
    const float* ln2b  = (const float*)d_in[6];
    const float* Wq    = (const float*)d_in[7];
    const float* bq    = (const float*)d_in[8];
    const float* Wk    = (const float*)d_in[9];
    const float* bk    = (const float*)d_in[10];
    const float* Wv    = (const float*)d_in[11];
    const float* bv    = (const float*)d_in[12];
    const float* Wrel  = (const float*)d_in[13];
    const float* brel  = (const float*)d_in[14];
    const float* Wproj = (const float*)d_in[15];
    const float* bproj = (const float*)d_in[16];
    const float* W1    = (const float*)d_in[17];
    const float* bW1   = (const float*)d_in[18];
    const float* gng   = (const float*)d_in[19];
    const float* gnb   = (const float*)d_in[20];
    const float* Wdw   = (const float*)d_in[21];
    const float* W2    = (const float*)d_in[22];
    const float* bW2   = (const float*)d_in[23];
    float* out = (float*)d_out;

    float *qln, *kln, *vln, *Q, *K, *V, *att, *tmp, *ln2, *h1, *ga, *cv;
    cudaGetSymbolAddress((void**)&qln, g_qln);
    cudaGetSymbolAddress((void**)&kln, g_kln);
    cudaGetSymbolAddress((void**)&vln, g_vln);
    cudaGetSymbolAddress((void**)&Q,   g_Q);
    cudaGetSymbolAddress((void**)&K,   g_K);
    cudaGetSymbolAddress((void**)&V,   g_V);
    cudaGetSymbolAddress((void**)&att, g_att);
    cudaGetSymbolAddress((void**)&tmp, g_tmp);
    cudaGetSymbolAddress((void**)&ln2, g_ln2);
    cudaGetSymbolAddress((void**)&h1,  g_h1);
    cudaGetSymbolAddress((void**)&ga,  g_ga);
    cudaGetSymbolAddress((void**)&cv,  g_cv);

    // 1. LayerNorms of q/k/v sources
    ln3_kernel<<<TOK, 256>>>(img, imw, msk, ln1g, ln1b);

    // 2. QKV projections
    gemm_kernel<<<dim3(Cd/64, TOK/64), 256>>>(qln, Wq, bq, Q, TOK, Cd, Cd);
    gemm_kernel<<<dim3(Cd/64, TOK/64), 256>>>(kln, Wk, bk, K, TOK, Cd, Cd);
    gemm_kernel<<<dim3(Cd/64, TOK/64), 256>>>(vln, Wv, bv, V, TOK, Cd, Cd);

    // 3. windowed attention
    attn_kernel<<<dim3(TOK, NHd), 256>>>(Wrel, brel);

    // 4. output projection + residual
    gemm_kernel<<<dim3(Cd/64, TOK/64), 256>>>(att, Wproj, bproj, tmp, TOK, Cd, Cd);
    addres_kernel<<<(TOK*Cd)/256, 256>>>(img);

    // 5. MLP branch
    ln_tok_kernel<<<TOK, 256>>>(ln2g, ln2b);
    gemm_kernel<<<dim3(HIDd/64, TOK/64), 256>>>(ln2, W1, bW1, h1, TOK, HIDd, Cd);
    gn_stats_kernel<<<Bz*GNg, 256>>>();
    gn_gelu_kernel<<<(TOK*HIDd)/256, 256>>>(gng, gnb);
    dwconv_kernel<<<(TOK*HIDd)/256, 256>>>(Wdw);
    gemm_kernel<<<dim3(Cd/64, TOK/64), 256>>>(cv, W2, bW2, tmp, TOK, Cd, HIDd);

    // 6. final residual + layout back to BCHW
    final_kernel<<<(Bz*Cd*HW)/256, 256>>>(out);
}

// round 2
// speedup vs baseline: 2.6970x; 2.6970x over previous
#include <cuda_runtime.h>
#include <math.h>

#define Bz   2
#define Cd   256
#define Hh   40
#define Wd   40
#define HW   1600
#define TOK  3200          // Bz*HW
#define NHd  8
#define HDd  32
#define WSd  15
#define W2Sd 225
#define MDd  7
#define HIDd 1024
#define GNg  32
#define EPSf 1e-5f
#define NEGINF -1e38f

// attention tiling
#define QT   4             // 4x4 query tile
#define EXT  18            // QT + 2*MD
#define EXT2 (EXT*EXT)     // 324
#define KPAD 325           // pad for conflict-free transpose store
#define WPAD 225
#define SPAD 228

// ---------------- scratch (device globals; no allocation) ----------------
__device__ float g_qln[TOK*Cd];
__device__ float g_kln[TOK*Cd];
__device__ float g_vln[TOK*Cd];
__device__ float g_Q[TOK*Cd];
__device__ float g_K[TOK*Cd];
__device__ float g_V[TOK*Cd];
__device__ float g_att[TOK*Cd];
__device__ float g_tmp[TOK*Cd];    // proj out / mlp out
__device__ float g_x1[TOK*Cd];     // residual after attention
__device__ float g_ln2[TOK*Cd];
__device__ float g_h1[TOK*HIDd];
__device__ float g_ga[TOK*HIDd];
__device__ float g_cv[TOK*HIDd];
__device__ float g_gnm[Bz*GNg*2];  // mean, rstd per (b, group)

// ---------------- fused LN of img / img_warp / img_warp+mask ----------------
__global__ void ln3_kernel(const float* __restrict__ img,
                           const float* __restrict__ imw,
                           const float* __restrict__ msk,
                           const float* __restrict__ g1,
                           const float* __restrict__ b1) {
    int tok = blockIdx.x;
    int c   = threadIdx.x;
    int b   = tok / HW, pos = tok % HW;
    int off = (b*Cd + c)*HW + pos;

    float x0 = img[off];
    float x1 = imw[off];
    float x2 = x1 + msk[off];
    float gg = g1[c], bb = b1[c];

    __shared__ float ssum[256];
    __shared__ float ssq[256];

    float vals[3] = {x0, x1, x2};
    float* outs[3] = {g_qln, g_kln, g_vln};

    for (int r = 0; r < 3; r++) {
        float v = vals[r];
        ssum[c] = v; ssq[c] = v*v;
        __syncthreads();
        for (int st = 128; st > 0; st >>= 1) {
            if (c < st) { ssum[c] += ssum[c+st]; ssq[c] += ssq[c+st]; }
            __syncthreads();
        }
        float mu  = ssum[0] * (1.0f/Cd);
        float var = ssq[0]  * (1.0f/Cd) - mu*mu;
        __syncthreads();
        outs[r][tok*Cd + c] = (v - mu) * rsqrtf(var + EPSf) * gg + bb;
    }
}

// ---------------- LN on token-major buffer ----------------
__global__ void ln_tok_kernel(const float* __restrict__ g1,
                              const float* __restrict__ b1) {
    int tok = blockIdx.x;
    int c   = threadIdx.x;
    float v = g_x1[tok*Cd + c];

    __shared__ float ssum[256];
    __shared__ float ssq[256];
    ssum[c] = v; ssq[c] = v*v;
    __syncthreads();
    for (int st = 128; st > 0; st >>= 1) {
        if (c < st) { ssum[c] += ssum[c+st]; ssq[c] += ssq[c+st]; }
        __syncthreads();
    }
    float mu  = ssum[0] * (1.0f/Cd);
    float var = ssq[0]  * (1.0f/Cd) - mu*mu;
    g_ln2[tok*Cd + c] = (v - mu) * rsqrtf(var + EPSf) * g1[c] + b1[c];
}

// ---------------- tiled fp32 GEMM core ----------------
__device__ __forceinline__ void gemm_body(const float* __restrict__ A,
                                          const float* __restrict__ W,
                                          const float* __restrict__ bias,
                                          float* __restrict__ C,
                                          int N, int K,
                                          int m0, int n0) {
    __shared__ float As[16][65];
    __shared__ float Ws[16][65];
    int tid = threadIdx.x;
    int tx = tid & 15, ty = tid >> 4;

    float acc[4][4] = {};

    for (int k0 = 0; k0 < K; k0 += 16) {
        #pragma unroll
        for (int i = 0; i < 4; i++) {
            int l = tid + i*256;
            int m = l >> 4, k = l & 15;
            As[k][m] = A[(m0+m)*K + k0 + k];
            Ws[k][m] = W[(n0+m)*K + k0 + k];
        }
        __syncthreads();
        #pragma unroll
        for (int k = 0; k < 16; k++) {
            float ra[4], rb[4];
            #pragma unroll
            for (int i = 0; i < 4; i++) ra[i] = As[k][ty*4+i];
            #pragma unroll
            for (int j = 0; j < 4; j++) rb[j] = Ws[k][tx*4+j];
            #pragma unroll
            for (int i = 0; i < 4; i++)
                #pragma unroll
                for (int j = 0; j < 4; j++)
                    acc[i][j] += ra[i]*rb[j];
        }
        __syncthreads();
    }

    #pragma unroll
    for (int i = 0; i < 4; i++) {
        #pragma unroll
        for (int j = 0; j < 4; j++) {
            int n = n0 + tx*4 + j;
            C[(m0+ty*4+i)*N + n] = acc[i][j] + bias[n];
        }
    }
}

__global__ void gemm_kernel(const float* __restrict__ A,
                            const float* __restrict__ W,
                            const float* __restrict__ bias,
                            float* __restrict__ C,
                            int N, int K) {
    gemm_body(A, W, bias, C, N, K, blockIdx.y*64, blockIdx.x*64);
}

// batched QKV projection (grid.z selects which)
struct QKVArgs {
    const float* A[3];
    const float* W[3];
    const float* bias[3];
    float* C[3];
};
__global__ void gemm_qkv_kernel(QKVArgs args) {
    int z = blockIdx.z;
    gemm_body(args.A[z], args.W[z], args.bias[z], args.C[z],
              Cd, Cd, blockIdx.y*64, blockIdx.x*64);
}

// ---------------- tiled local attention ----------------
// grid: (100 tiles, NH, B), 256 threads, dynamic smem
__global__ void attn_tile_kernel(const float* __restrict__ Wrel,
                                 const float* __restrict__ brel) {
    extern __shared__ float smem[];
    float* sK   = smem;                    // [32][KPAD]  K window (then V)
    float* sW   = sK + 32*KPAD;            // [32][WPAD]  Wrel for this head
    float* sS   = sW + 32*WPAD;            // [16][SPAD]  scores -> probs
    float* sInv = sS + 16*SPAD;            // [16]        1/sum per query

    int tile = blockIdx.x;
    int h = blockIdx.y, b = blockIdx.z;
    int ty0 = (tile / (Wd/QT)) * QT;
    int tx0 = (tile % (Wd/QT)) * QT;
    int t = threadIdx.x;

    // load Wrel[h] (225 x 32) transposed
    for (int i = t; i < W2Sd*32; i += 256) {
        int o = i >> 5, c = i & 31;
        sW[c*WPAD + o] = Wrel[(h*W2Sd + o)*HDd + c];
    }
    // load K window (18x18x32), transposed, zero-padded OOB
    int wy0 = ty0 - MDd, wx0 = tx0 - MDd;
    for (int i = t; i < EXT2*32; i += 256) {
        int pos = i >> 5, c = i & 31;
        int wy = pos / EXT, wx = pos - (pos/EXT)*EXT;
        int ky = wy0 + wy, kx = wx0 + wx;
        float v = 0.f;
        if (ky >= 0 && ky < Hh && kx >= 0 && kx < Wd)
            v = g_K[(size_t)(b*HW + ky*Wd + kx)*Cd + h*HDd + c];
        sK[c*KPAD + pos] = v;
    }

    // q into registers
    int q  = t >> 4;            // query index 0..15
    int lo = t & 15;            // offset lane
    int qy = q >> 2, qx = q & 3;
    int ty = ty0 + qy, tx = tx0 + qx;
    int tok = b*HW + ty*Wd + tx;
    float qreg[32];
    {
        const float* qp = g_Q + (size_t)tok*Cd + h*HDd;
        #pragma unroll
        for (int c = 0; c < 32; c++) qreg[c] = qp[c];
    }
    __syncthreads();

    // scores: each thread handles offsets o = lo, lo+16, ...
    const float scale = 0.17677669529663687f;  // 1/sqrt(32)
    for (int o = lo; o < W2Sd; o += 16) {
        int oy = o / WSd, ox = o - (o/WSd)*WSd;
        int ky = ty + oy - MDd, kx = tx + ox - MDd;
        float s = NEGINF;
        if (ky >= 0 && ky < Hh && kx >= 0 && kx < Wd) {
            int pos = (qy + oy)*EXT + (qx + ox);
            float d = 0.f, r = 0.f;
            #pragma unroll
            for (int c = 0; c < 32; c++) {
                d += qreg[c] * sK[c*KPAD + pos];
                r += qreg[c] * sW[c*WPAD + o];
            }
            s = d*scale + r + brel[h*W2Sd + o];
        }
        sS[q*SPAD + o] = s;
    }
    __syncthreads();

    // softmax over 225 per query: 16 lanes per query, shuffle reduce
    {
        float mx = NEGINF;
        for (int o = lo; o < W2Sd; o += 16)
            mx = fmaxf(mx, sS[q*SPAD + o]);
        #pragma unroll
        for (int d = 8; d > 0; d >>= 1)
            mx = fmaxf(mx, __shfl_xor_sync(0xffffffffu, mx, d));
        float sum = 0.f;
        for (int o = lo; o < W2Sd; o += 16) {
            float s = sS[q*SPAD + o];
            float e = (s > -1e37f) ? __expf(s - mx) : 0.f;
            sS[q*SPAD + o] = e;
            sum += e;
        }
        #pragma unroll
        for (int d = 8; d > 0; d >>= 1)
            sum += __shfl_xor_sync(0xffffffffu, sum, d);
        if (lo == 0) sInv[q] = 1.f / sum;
    }
    __syncthreads();

    // load V window into sK (reuse)
    for (int i = t; i < EXT2*32; i += 256) {
        int pos = i >> 5, c = i & 31;
        int wy = pos / EXT, wx = pos - (pos/EXT)*EXT;
        int ky = wy0 + wy, kx = wx0 + wx;
        float v = 0.f;
        if (ky >= 0 && ky < Hh && kx >= 0 && kx < Wd)
            v = g_V[(size_t)(b*HW + ky*Wd + kx)*Cd + h*HDd + c];
        sK[c*KPAD + pos] = v;
    }
    __syncthreads();

    // weighted V sum: thread = (channel, query-half)
    int c = t & 31, q8 = t >> 5;
    #pragma unroll
    for (int rep = 0; rep < 2; rep++) {
        int qq = q8 + rep*8;
        int qqy = qq >> 2, qqx = qq & 3;
        float acc = 0.f;
        #pragma unroll
        for (int oy = 0; oy < WSd; oy++) {
            int rowbase = (qqy + oy)*EXT + qqx;
            int srow = qq*SPAD + oy*WSd;
            #pragma unroll
            for (int ox = 0; ox < WSd; ox++)
                acc += sS[srow + ox] * sK[c*KPAD + rowbase + ox];
        }
        int tok2 = b*HW + (ty0 + qqy)*Wd + (tx0 + qqx);
        g_att[(size_t)tok2*Cd + h*HDd + c] = acc * sInv[qq];
    }
}

// ---------------- residual: x1 = proj_out + img tokens ----------------
__global__ void addres_kernel(const float* __restrict__ img) {
    int idx = blockIdx.x*256 + threadIdx.x;
    int tok = idx / Cd, c = idx % Cd;
    int b = tok / HW, pos = tok % HW;
    g_x1[idx] = g_tmp[idx] + img[(b*Cd + c)*HW + pos];
}

// ---------------- GroupNorm stats per (b, group) ----------------
__global__ void gn_stats_kernel() {
    int bg = blockIdx.x;
    int b = bg / GNg, g = bg % GNg;
    int tid = threadIdx.x;
    float sm = 0.f, sq = 0.f;
    for (int i = tid; i < HW*32; i += 256) {
        int ch  = g*32 + (i & 31);
        int pos = i >> 5;
        float v = g_h1[(size_t)(b*HW + pos)*HIDd + ch];
        sm += v; sq += v*v;
    }
    __shared__ float s1[256], s2[256];
    s1[tid] = sm; s2[tid] = sq;
    __syncthreads();
    for (int st = 128; st > 0; st >>= 1) {
        if (tid < st) { s1[tid] += s1[tid+st]; s2[tid] += s2[tid+st]; }
        __syncthreads();
    }
    if (tid == 0) {
        float cnt = (float)(HW*32);
        float mu  = s1[0] / cnt;
        float var = s2[0] / cnt - mu*mu;
        g_gnm[bg*2]   = mu;
        g_gnm[bg*2+1] = rsqrtf(var + EPSf);
    }
}

// ---------------- GN normalize + exact GELU ----------------
__global__ void gn_gelu_kernel(const float* __restrict__ gg,
                               const float* __restrict__ gb) {
    int idx = blockIdx.x*256 + threadIdx.x;
    int ch  = idx % HIDd;
    int tok = idx / HIDd;
    int b   = tok / HW;
    int grp = ch >> 5;
    float mu = g_gnm[(b*GNg + grp)*2];
    float rs = g_gnm[(b*GNg + grp)*2 + 1];
    float v  = (g_h1[idx] - mu) * rs * gg[ch] + gb[ch];
    g_ga[idx] = 0.5f * v * (1.f + erff(v * 0.70710678118654752f));
}

// ---------------- 5x5 depthwise conv, pad 2, no bias ----------------
__global__ void dwconv_kernel(const float* __restrict__ Wdw) {
    int idx = blockIdx.x*256 + threadIdx.x;
    int ch  = idx % HIDd;
    int tok = idx / HIDd;
    int b   = tok / HW, pos = tok % HW;
    int y   = pos / Wd, x = pos % Wd;
    float acc = 0.f;
    #pragma unroll
    for (int dy = 0; dy < 5; dy++) {
        int yy = y + dy - 2;
        if (yy < 0 || yy >= Hh) continue;
        #pragma unroll
        for (int dx = 0; dx < 5; dx++) {
            int xx = x + dx - 2;
            if (xx < 0 || xx >= Wd) continue;
            acc += Wdw[ch*25 + dy*5 + dx] *
                   g_ga[(size_t)(b*HW + yy*Wd + xx)*HIDd + ch];
        }
    }
    g_cv[idx] = acc;
}

// ---------------- final: out[BCHW] = x1 + mlp_out ----------------
__global__ void final_kernel(float* __restrict__ out) {
    int idx = blockIdx.x*256 + threadIdx.x;   // BCHW index
    int pos = idx % HW;
    int bc  = idx / HW;
    int c   = bc % Cd, b = bc / Cd;
    int t   = (b*HW + pos)*Cd + c;
    out[idx] = g_x1[t] + g_tmp[t];
}

// ---------------- launch ----------------
extern "C" void kernel_launch(void* const* d_in, const int* in_sizes, int n_in,
                              void* d_out, int out_size) {
    const float* img   = (const float*)d_in[0];
    const float* imw   = (const float*)d_in[1];
    const float* msk   = (const float*)d_in[2];
    const float* ln1g  = (const float*)d_in[3];
    const float* ln1b  = (const float*)d_in[4];
    const float* ln2g  = (const float*)d_in[5];
    const float* ln2b  = (const float*)d_in[6];
    const float* Wq    = (const float*)d_in[7];
    const float* bq    = (const float*)d_in[8];
    const float* Wk    = (const float*)d_in[9];
    const float* bk    = (const float*)d_in[10];
    const float* Wv    = (const float*)d_in[11];
    const float* bv    = (const float*)d_in[12];
    const float* Wrel  = (const float*)d_in[13];
    const float* brel  = (const float*)d_in[14];
    const float* Wproj = (const float*)d_in[15];
    const float* bproj = (const float*)d_in[16];
    const float* W1    = (const float*)d_in[17];
    const float* bW1   = (const float*)d_in[18];
    const float* gng   = (const float*)d_in[19];
    const float* gnb   = (const float*)d_in[20];
    const float* Wdw   = (const float*)d_in[21];
    const float* W2    = (const float*)d_in[22];
    const float* bW2   = (const float*)d_in[23];
    float* out = (float*)d_out;

    float *qln, *kln, *vln, *Q, *K, *V, *att, *tmp, *ln2, *h1, *ga, *cv;
    cudaGetSymbolAddress((void**)&qln, g_qln);
    cudaGetSymbolAddress((void**)&kln, g_kln);
    cudaGetSymbolAddress((void**)&vln, g_vln);
    cudaGetSymbolAddress((void**)&Q,   g_Q);
    cudaGetSymbolAddress((void**)&K,   g_K);
    cudaGetSymbolAddress((void**)&V,   g_V);
    cudaGetSymbolAddress((void**)&att, g_att);
    cudaGetSymbolAddress((void**)&tmp, g_tmp);
    cudaGetSymbolAddress((void**)&ln2, g_ln2);
    cudaGetSymbolAddress((void**)&h1,  g_h1);
    cudaGetSymbolAddress((void**)&ga,  g_ga);
    cudaGetSymbolAddress((void**)&cv,  g_cv);

    // 1. LayerNorms of q/k/v sources
    ln3_kernel<<<TOK, 256>>>(img, imw, msk, ln1g, ln1b);

    // 2. QKV projections (batched, grid.z = 3)
    QKVArgs qa;
    qa.A[0] = qln; qa.A[1] = kln; qa.A[2] = vln;
    qa.W[0] = Wq;  qa.W[1] = Wk;  qa.W[2] = Wv;
    qa.bias[0] = bq; qa.bias[1] = bk; qa.bias[2] = bv;
    qa.C[0] = Q; qa.C[1] = K; qa.C[2] = V;
    gemm_qkv_kernel<<<dim3(Cd/64, TOK/64, 3), 256>>>(qa);

    // 3. tiled windowed attention
    int smem_bytes = (32*KPAD + 32*WPAD + 16*SPAD + 16) * sizeof(float);
    cudaFuncSetAttribute(attn_tile_kernel,
                         cudaFuncAttributeMaxDynamicSharedMemorySize, smem_bytes);
    attn_tile_kernel<<<dim3((Hh/QT)*(Wd/QT), NHd, Bz), 256, smem_bytes>>>(Wrel, brel);

    // 4. output projection + residual
    gemm_kernel<<<dim3(Cd/64, TOK/64), 256>>>(att, Wproj, bproj, tmp, Cd, Cd);
    addres_kernel<<<(TOK*Cd)/256, 256>>>(img);

    // 5. MLP branch
    ln_tok_kernel<<<TOK, 256>>>(ln2g, ln2b);
    gemm_kernel<<<dim3(HIDd/64, TOK/64), 256>>>(ln2, W1, bW1, h1, HIDd, Cd);
    gn_stats_kernel<<<Bz*GNg, 256>>>();
    gn_gelu_kernel<<<(TOK*HIDd)/256, 256>>>(gng, gnb);
    dwconv_kernel<<<(TOK*HIDd)/256, 256>>>(Wdw);
    gemm_kernel<<<dim3(Cd/64, TOK/64), 256>>>(cv, W2, bW2, tmp, Cd, HIDd);

    // 6. final residual + layout back to BCHW
    final_kernel<<<(Bz*Cd*HW)/256, 256>>>(out);
}

// round 3
// speedup vs baseline: 4.0166x; 1.4893x over previous
#include <cuda_runtime.h>
#include <math.h>

#define Bz   2
#define Cd   256
#define Hh   40
#define Wd   40
#define HW   1600
#define TOK  3200          // Bz*HW
#define NHd  8
#define HDd  32
#define WSd  15
#define W2Sd 225
#define MDd  7
#define HIDd 1024
#define GNg  32
#define EPSf 1e-5f
#define NEGINF -1e38f

// attention tiling
#define QT   4             // 4x4 query tile
#define EXT  18            // QT + 2*MD
#define EXT2 (EXT*EXT)     // 324
#define KPAD 325
#define WPAD 225
#define SPAD 228

// ---------------- scratch (device globals; no allocation) ----------------
__device__ float g_qln[TOK*Cd];
__device__ float g_kln[TOK*Cd];
__device__ float g_vln[TOK*Cd];
__device__ float g_Q[TOK*Cd];
__device__ float g_K[TOK*Cd];
__device__ float g_V[TOK*Cd];
__device__ float g_att[TOK*Cd];
__device__ float g_x1[TOK*Cd];     // residual after attention
__device__ float g_ln2[TOK*Cd];
__device__ float g_h1[TOK*HIDd];
__device__ float g_ga[TOK*HIDd];
__device__ float g_cv[TOK*HIDd];
__device__ float g_gnm[Bz*GNg*2];  // mean, rstd per (b, group)

// ---------------- block mean/var helper (256 threads) ----------------
__device__ __forceinline__ void block_meanvar(float v, float* sbuf,
                                              float& mu, float& rstd) {
    float s = v, q = v*v;
    #pragma unroll
    for (int d = 16; d > 0; d >>= 1) {
        s += __shfl_xor_sync(0xffffffffu, s, d);
        q += __shfl_xor_sync(0xffffffffu, q, d);
    }
    int warp = threadIdx.x >> 5, lane = threadIdx.x & 31;
    if (lane == 0) { sbuf[warp] = s; sbuf[8 + warp] = q; }
    __syncthreads();
    if (warp == 0) {
        float ss = (lane < 8) ? sbuf[lane] : 0.f;
        float qq = (lane < 8) ? sbuf[8 + lane] : 0.f;
        #pragma unroll
        for (int d = 4; d > 0; d >>= 1) {
            ss += __shfl_xor_sync(0xffffffffu, ss, d);
            qq += __shfl_xor_sync(0xffffffffu, qq, d);
        }
        if (lane == 0) {
            float m = ss * (1.0f/Cd);
            float var = qq * (1.0f/Cd) - m*m;
            sbuf[16] = m;
            sbuf[17] = rsqrtf(var + EPSf);
        }
    }
    __syncthreads();
    mu = sbuf[16]; rstd = sbuf[17];
}

// ---------------- fused LN of img / img_warp / img_warp+mask ----------------
__global__ void ln3_kernel(const float* __restrict__ img,
                           const float* __restrict__ imw,
                           const float* __restrict__ msk,
                           const float* __restrict__ g1,
                           const float* __restrict__ b1) {
    int tok = blockIdx.x;
    int c   = threadIdx.x;
    int b   = tok / HW, pos = tok % HW;
    int off = (b*Cd + c)*HW + pos;

    float x0 = img[off];
    float x1 = imw[off];
    float x2 = x1 + msk[off];
    float gg = g1[c], bb = b1[c];

    __shared__ float sbuf[18];
    float mu, rs;

    block_meanvar(x0, sbuf, mu, rs);
    g_qln[tok*Cd + c] = (x0 - mu) * rs * gg + bb;
    __syncthreads();
    block_meanvar(x1, sbuf, mu, rs);
    g_kln[tok*Cd + c] = (x1 - mu) * rs * gg + bb;
    __syncthreads();
    block_meanvar(x2, sbuf, mu, rs);
    g_vln[tok*Cd + c] = (x2 - mu) * rs * gg + bb;
}

// ---------------- LN on token-major buffer ----------------
__global__ void ln_tok_kernel(const float* __restrict__ g1,
                              const float* __restrict__ b1) {
    int tok = blockIdx.x;
    int c   = threadIdx.x;
    float v = g_x1[tok*Cd + c];
    __shared__ float sbuf[18];
    float mu, rs;
    block_meanvar(v, sbuf, mu, rs);
    g_ln2[tok*Cd + c] = (v - mu) * rs * g1[c] + b1[c];
}

// ---------------- tf32 tensor-core GEMM ----------------
// C[M,N] = A[M,K] * W[N,K]^T + bias. BM=BN=64, BK=16, 128 threads, 4 warps.
// mode 0: C[m*N+n] = v
// mode 1: C[m*N+n] = v + res[(b*Cd+n)*HW+pos]   (residual from BCHW img)
// mode 2: out[(b*Cd+n)*HW+pos] = v + res[m*N+n] (final residual + transpose)
__device__ __forceinline__ unsigned f2tf32(float x) {
    unsigned r;
    asm("cvt.rna.tf32.f32 %0, %1;" : "=r"(r) : "f"(x));
    return r;
}

__device__ __forceinline__ void mma_body(const float* __restrict__ A,
                                         const float* __restrict__ Wt,
                                         const float* __restrict__ bias,
                                         float* __restrict__ C,
                                         int N, int K, int m0, int n0,
                                         int mode, const float* __restrict__ res) {
    __shared__ float As[64][20];
    __shared__ float Ws[64][20];
    int tid  = threadIdx.x;
    int lane = tid & 31, warp = tid >> 5;
    int wm = (warp >> 1) * 32, wn = (warp & 1) * 32;
    int g = lane >> 2, t4 = lane & 3;

    float acc[2][4][4] = {};

    for (int k0 = 0; k0 < K; k0 += 16) {
        #pragma unroll
        for (int r = 0; r < 2; r++) {
            int idx = tid*2 + r;                 // 0..255
            int row = idx >> 2, cv = (idx & 3) * 4;
            *(float4*)&As[row][cv] =
                *(const float4*)&A[(size_t)(m0+row)*K + k0 + cv];
            *(float4*)&Ws[row][cv] =
                *(const float4*)&Wt[(size_t)(n0+row)*K + k0 + cv];
        }
        __syncthreads();
        #pragma unroll
        for (int ks = 0; ks < 16; ks += 8) {
            unsigned a[2][4], bf[4][2];
            #pragma unroll
            for (int mt = 0; mt < 2; mt++) {
                int rb = wm + mt*16;
                a[mt][0] = f2tf32(As[rb + g    ][ks + t4    ]);
                a[mt][1] = f2tf32(As[rb + g + 8][ks + t4    ]);
                a[mt][2] = f2tf32(As[rb + g    ][ks + t4 + 4]);
                a[mt][3] = f2tf32(As[rb + g + 8][ks + t4 + 4]);
            }
            #pragma unroll
            for (int nt = 0; nt < 4; nt++) {
                int nb = wn + nt*8 + g;
                bf[nt][0] = f2tf32(Ws[nb][ks + t4    ]);
                bf[nt][1] = f2tf32(Ws[nb][ks + t4 + 4]);
            }
            #pragma unroll
            for (int mt = 0; mt < 2; mt++)
                #pragma unroll
                for (int nt = 0; nt < 4; nt++)
                    asm volatile(
                        "mma.sync.aligned.m16n8k8.row.col.f32.tf32.tf32.f32 "
                        "{%0,%1,%2,%3}, {%4,%5,%6,%7}, {%8,%9}, {%0,%1,%2,%3};"
                        : "+f"(acc[mt][nt][0]), "+f"(acc[mt][nt][1]),
                          "+f"(acc[mt][nt][2]), "+f"(acc[mt][nt][3])
                        : "r"(a[mt][0]), "r"(a[mt][1]),
                          "r"(a[mt][2]), "r"(a[mt][3]),
                          "r"(bf[nt][0]), "r"(bf[nt][1]));
        }
        __syncthreads();
    }

    #pragma unroll
    for (int mt = 0; mt < 2; mt++) {
        #pragma unroll
        for (int nt = 0; nt < 4; nt++) {
            #pragma unroll
            for (int i = 0; i < 4; i++) {
                int mrow = m0 + wm + mt*16 + g + ((i >= 2) ? 8 : 0);
                int ncol = n0 + wn + nt*8 + 2*t4 + (i & 1);
                float v = acc[mt][nt][i] + bias[ncol];
                if (mode == 0) {
                    C[(size_t)mrow*N + ncol] = v;
                } else if (mode == 1) {
                    int b = mrow / HW, pos = mrow % HW;
                    C[(size_t)mrow*N + ncol] =
                        v + res[(size_t)(b*Cd + ncol)*HW + pos];
                } else {
                    int b = mrow / HW, pos = mrow % HW;
                    C[(size_t)(b*Cd + ncol)*HW + pos] =
                        v + res[(size_t)mrow*N + ncol];
                }
            }
        }
    }
}

__global__ void mma_gemm_kernel(const float* __restrict__ A,
                                const float* __restrict__ Wt,
                                const float* __restrict__ bias,
                                float* __restrict__ C,
                                int N, int K, int mode,
                                const float* __restrict__ res) {
    mma_body(A, Wt, bias, C, N, K, blockIdx.y*64, blockIdx.x*64, mode, res);
}

struct QKVArgs {
    const float* A[3];
    const float* W[3];
    const float* bias[3];
    float* C[3];
};
__global__ void mma_qkv_kernel(QKVArgs args) {
    int z = blockIdx.z;
    mma_body(args.A[z], args.W[z], args.bias[z], args.C[z],
             Cd, Cd, blockIdx.y*64, blockIdx.x*64, 0, nullptr);
}

// ---------------- tiled local attention ----------------
__global__ void attn_tile_kernel(const float* __restrict__ Wrel,
                                 const float* __restrict__ brel) {
    extern __shared__ float smem[];
    float* sK   = smem;                    // [32][KPAD]  K window (then V)
    float* sW   = sK + 32*KPAD;            // [32][WPAD]  Wrel for this head
    float* sS   = sW + 32*WPAD;            // [16][SPAD]  scores -> probs
    float* sInv = sS + 16*SPAD;            // [16]

    int tile = blockIdx.x;
    int h = blockIdx.y, b = blockIdx.z;
    int ty0 = (tile / (Wd/QT)) * QT;
    int tx0 = (tile % (Wd/QT)) * QT;
    int t = threadIdx.x;

    for (int i = t; i < W2Sd*32; i += 256) {
        int o = i >> 5, c = i & 31;
        sW[c*WPAD + o] = Wrel[(h*W2Sd + o)*HDd + c];
    }
    int wy0 = ty0 - MDd, wx0 = tx0 - MDd;
    for (int i = t; i < EXT2*32; i += 256) {
        int pos = i >> 5, c = i & 31;
        int wy = pos / EXT, wx = pos - (pos/EXT)*EXT;
        int ky = wy0 + wy, kx = wx0 + wx;
        float v = 0.f;
        if (ky >= 0 && ky < Hh && kx >= 0 && kx < Wd)
            v = g_K[(size_t)(b*HW + ky*Wd + kx)*Cd + h*HDd + c];
        sK[c*KPAD + pos] = v;
    }

    int q  = t >> 4;
    int lo = t & 15;
    int qy = q >> 2, qx = q & 3;
    int ty = ty0 + qy, tx = tx0 + qx;
    int tok = b*HW + ty*Wd + tx;
    float qreg[32];
    {
        const float* qp = g_Q + (size_t)tok*Cd + h*HDd;
        #pragma unroll
        for (int c = 0; c < 32; c++) qreg[c] = qp[c];
    }
    __syncthreads();

    const float scale = 0.17677669529663687f;
    for (int o = lo; o < W2Sd; o += 16) {
        int oy = o / WSd, ox = o - (o/WSd)*WSd;
        int ky = ty + oy - MDd, kx = tx + ox - MDd;
        float s = NEGINF;
        if (ky >= 0 && ky < Hh && kx >= 0 && kx < Wd) {
            int pos = (qy + oy)*EXT + (qx + ox);
            float d = 0.f, r = 0.f;
            #pragma unroll
            for (int c = 0; c < 32; c++) {
                d += qreg[c] * sK[c*KPAD + pos];
                r += qreg[c] * sW[c*WPAD + o];
            }
            s = d*scale + r + brel[h*W2Sd + o];
        }
        sS[q*SPAD + o] = s;
    }
    __syncthreads();

    {
        float mx = NEGINF;
        for (int o = lo; o < W2Sd; o += 16)
            mx = fmaxf(mx, sS[q*SPAD + o]);
        #pragma unroll
        for (int d = 8; d > 0; d >>= 1)
            mx = fmaxf(mx, __shfl_xor_sync(0xffffffffu, mx, d));
        float sum = 0.f;
        for (int o = lo; o < W2Sd; o += 16) {
            float s = sS[q*SPAD + o];
            float e = (s > -1e37f) ? __expf(s - mx) : 0.f;
            sS[q*SPAD + o] = e;
            sum += e;
        }
        #pragma unroll
        for (int d = 8; d > 0; d >>= 1)
            sum += __shfl_xor_sync(0xffffffffu, sum, d);
        if (lo == 0) sInv[q] = 1.f / sum;
    }
    __syncthreads();

    for (int i = t; i < EXT2*32; i += 256) {
        int pos = i >> 5, c = i & 31;
        int wy = pos / EXT, wx = pos - (pos/EXT)*EXT;
        int ky = wy0 + wy, kx = wx0 + wx;
        float v = 0.f;
        if (ky >= 0 && ky < Hh && kx >= 0 && kx < Wd)
            v = g_V[(size_t)(b*HW + ky*Wd + kx)*Cd + h*HDd + c];
        sK[c*KPAD + pos] = v;
    }
    __syncthreads();

    int c = t & 31, q8 = t >> 5;
    #pragma unroll
    for (int rep = 0; rep < 2; rep++) {
        int qq = q8 + rep*8;
        int qqy = qq >> 2, qqx = qq & 3;
        float acc = 0.f;
        #pragma unroll
        for (int oy = 0; oy < WSd; oy++) {
            int rowbase = (qqy + oy)*EXT + qqx;
            int srow = qq*SPAD + oy*WSd;
            #pragma unroll
            for (int ox = 0; ox < WSd; ox++)
                acc += sS[srow + ox] * sK[c*KPAD + rowbase + ox];
        }
        int tok2 = b*HW + (ty0 + qqy)*Wd + (tx0 + qqx);
        g_att[(size_t)tok2*Cd + h*HDd + c] = acc * sInv[qq];
    }
}

// ---------------- GroupNorm stats per (b, group) ----------------
__global__ void gn_stats_kernel() {
    int bg = blockIdx.x;
    int b = bg / GNg, g = bg % GNg;
    int tid = threadIdx.x;
    float sm = 0.f, sq = 0.f;
    for (int i = tid; i < HW*32; i += 256) {
        int ch  = g*32 + (i & 31);
        int pos = i >> 5;
        float v = g_h1[(size_t)(b*HW + pos)*HIDd + ch];
        sm += v; sq += v*v;
    }
    #pragma unroll
    for (int d = 16; d > 0; d >>= 1) {
        sm += __shfl_xor_sync(0xffffffffu, sm, d);
        sq += __shfl_xor_sync(0xffffffffu, sq, d);
    }
    __shared__ float s1[8], s2[8];
    int warp = tid >> 5, lane = tid & 31;
    if (lane == 0) { s1[warp] = sm; s2[warp] = sq; }
    __syncthreads();
    if (tid == 0) {
        float ss = 0.f, qq = 0.f;
        #pragma unroll
        for (int i = 0; i < 8; i++) { ss += s1[i]; qq += s2[i]; }
        float cnt = (float)(HW*32);
        float mu  = ss / cnt;
        float var = qq / cnt - mu*mu;
        g_gnm[bg*2]   = mu;
        g_gnm[bg*2+1] = rsqrtf(var + EPSf);
    }
}

// ---------------- GN normalize + exact GELU ----------------
__global__ void gn_gelu_kernel(const float* __restrict__ gg,
                               const float* __restrict__ gb) {
    int idx = blockIdx.x*256 + threadIdx.x;
    int ch  = idx % HIDd;
    int tok = idx / HIDd;
    int b   = tok / HW;
    int grp = ch >> 5;
    float mu = g_gnm[(b*GNg + grp)*2];
    float rs = g_gnm[(b*GNg + grp)*2 + 1];
    float v  = (g_h1[idx] - mu) * rs * gg[ch] + gb[ch];
    g_ga[idx] = 0.5f * v * (1.f + erff(v * 0.70710678118654752f));
}

// ---------------- 5x5 depthwise conv, pad 2, no bias ----------------
__global__ void dwconv_kernel(const float* __restrict__ Wdw) {
    int idx = blockIdx.x*256 + threadIdx.x;
    int ch  = idx % HIDd;
    int tok = idx / HIDd;
    int b   = tok / HW, pos = tok % HW;
    int y   = pos / Wd, x = pos % Wd;
    float acc = 0.f;
    #pragma unroll
    for (int dy = 0; dy < 5; dy++) {
        int yy = y + dy - 2;
        if (yy < 0 || yy >= Hh) continue;
        #pragma unroll
        for (int dx = 0; dx < 5; dx++) {
            int xx = x + dx - 2;
            if (xx < 0 || xx >= Wd) continue;
            acc += Wdw[ch*25 + dy*5 + dx] *
                   g_ga[(size_t)(b*HW + yy*Wd + xx)*HIDd + ch];
        }
    }
    g_cv[idx] = acc;
}

// ---------------- launch ----------------
extern "C" void kernel_launch(void* const* d_in, const int* in_sizes, int n_in,
                              void* d_out, int out_size) {
    const float* img   = (const float*)d_in[0];
    const float* imw   = (const float*)d_in[1];
    const float* msk   = (const float*)d_in[2];
    const float* ln1g  = (const float*)d_in[3];
    const float* ln1b  = (const float*)d_in[4];
    const float* ln2g  = (const float*)d_in[5];
    const float* ln2b  = (const float*)d_in[6];
    const float* Wq    = (const float*)d_in[7];
    const float* bq    = (const float*)d_in[8];
    const float* Wk    = (const float*)d_in[9];
    const float* bk    = (const float*)d_in[10];
    const float* Wv    = (const float*)d_in[11];
    const float* bv    = (const float*)d_in[12];
    const float* Wrel  = (const float*)d_in[13];
    const float* brel  = (const float*)d_in[14];
    const float* Wproj = (const float*)d_in[15];
    const float* bproj = (const float*)d_in[16];
    const float* W1    = (const float*)d_in[17];
    const float* bW1   = (const float*)d_in[18];
    const float* gng   = (const float*)d_in[19];
    const float* gnb   = (const float*)d_in[20];
    const float* Wdw   = (const float*)d_in[21];
    const float* W2    = (const float*)d_in[22];
    const float* bW2   = (const float*)d_in[23];
    float* out = (float*)d_out;

    float *qln, *kln, *vln, *Q, *K, *V, *att, *x1, *ln2, *h1, *cv;
    cudaGetSymbolAddress((void**)&qln, g_qln);
    cudaGetSymbolAddress((void**)&kln, g_kln);
    cudaGetSymbolAddress((void**)&vln, g_vln);
    cudaGetSymbolAddress((void**)&Q,   g_Q);
    cudaGetSymbolAddress((void**)&K,   g_K);
    cudaGetSymbolAddress((void**)&V,   g_V);
    cudaGetSymbolAddress((void**)&att, g_att);
    cudaGetSymbolAddress((void**)&x1,  g_x1);
    cudaGetSymbolAddress((void**)&ln2, g_ln2);
    cudaGetSymbolAddress((void**)&h1,  g_h1);
    cudaGetSymbolAddress((void**)&cv,  g_cv);

    // 1. LayerNorms of q/k/v sources
    ln3_kernel<<<TOK, 256>>>(img, imw, msk, ln1g, ln1b);

    // 2. QKV projections (tensor cores, batched grid.z=3)
    QKVArgs qa;
    qa.A[0] = qln; qa.A[1] = kln; qa.A[2] = vln;
    qa.W[0] = Wq;  qa.W[1] = Wk;  qa.W[2] = Wv;
    qa.bias[0] = bq; qa.bias[1] = bk; qa.bias[2] = bv;
    qa.C[0] = Q; qa.C[1] = K; qa.C[2] = V;
    mma_qkv_kernel<<<dim3(Cd/64, TOK/64, 3), 128>>>(qa);

    // 3. tiled windowed attention
    int smem_bytes = (32*KPAD + 32*WPAD + 16*SPAD + 16) * sizeof(float);
    cudaFuncSetAttribute(attn_tile_kernel,
                         cudaFuncAttributeMaxDynamicSharedMemorySize, smem_bytes);
    attn_tile_kernel<<<dim3((Hh/QT)*(Wd/QT), NHd, Bz), 256, smem_bytes>>>(Wrel, brel);

    // 4. output projection + fused residual (img gather) -> x1
    mma_gemm_kernel<<<dim3(Cd/64, TOK/64), 128>>>(att, Wproj, bproj, x1,
                                                  Cd, Cd, 1, img);

    // 5. MLP branch
    ln_tok_kernel<<<TOK, 256>>>(ln2g, ln2b);
    mma_gemm_kernel<<<dim3(HIDd/64, TOK/64), 128>>>(ln2, W1, bW1, h1,
                                                    HIDd, Cd, 0, nullptr);
    gn_stats_kernel<<<Bz*GNg, 256>>>();
    gn_gelu_kernel<<<(TOK*HIDd)/256, 256>>>(gng, gnb);
    dwconv_kernel<<<(TOK*HIDd)/256, 256>>>(Wdw);

    // 6. W2 + fused final residual + transpose to BCHW
    mma_gemm_kernel<<<dim3(Cd/64, TOK/64), 128>>>(cv, W2, bW2, out,
                                                  Cd, HIDd, 2, x1);
}

// round 4
// speedup vs baseline: 5.5896x; 1.3916x over previous
#include <cuda_runtime.h>
#include <math.h>

#define Bz   2
#define Cd   256
#define Hh   40
#define Wd   40
#define HW   1600
#define TOK  3200          // Bz*HW
#define NHd  8
#define HDd  32
#define WSd  15
#define W2Sd 225
#define MDd  7
#define HIDd 1024
#define GNg  32
#define EPSf 1e-5f
#define NEGINF -1e38f

// attention tiling
#define QT   4
#define EXT  18
#define EXT2 (EXT*EXT)
#define KPAD 325
#define WPAD 225
#define SPAD 228

// GEMM tiling
#define BM 128
#define BN 64
#define BK 32
#define KP 36              // padded K stride in smem (36*4=144B, 16B aligned)

// ---------------- scratch ----------------
__device__ float g_qln[TOK*Cd];
__device__ float g_kln[TOK*Cd];
__device__ float g_vln[TOK*Cd];
__device__ float g_Q[TOK*Cd];
__device__ float g_K[TOK*Cd];
__device__ float g_V[TOK*Cd];
__device__ float g_att[TOK*Cd];
__device__ float g_x1[TOK*Cd];
__device__ float g_ln2[TOK*Cd];
__device__ float g_h1[TOK*HIDd];
__device__ float g_cv[TOK*HIDd];
__device__ float g_gnm[Bz*GNg*2];

// ---------------- block mean/var helper (256 threads) ----------------
__device__ __forceinline__ void block_meanvar(float v, float* sbuf,
                                              float& mu, float& rstd) {
    float s = v, q = v*v;
    #pragma unroll
    for (int d = 16; d > 0; d >>= 1) {
        s += __shfl_xor_sync(0xffffffffu, s, d);
        q += __shfl_xor_sync(0xffffffffu, q, d);
    }
    int warp = threadIdx.x >> 5, lane = threadIdx.x & 31;
    if (lane == 0) { sbuf[warp] = s; sbuf[8 + warp] = q; }
    __syncthreads();
    if (warp == 0) {
        float ss = (lane < 8) ? sbuf[lane] : 0.f;
        float qq = (lane < 8) ? sbuf[8 + lane] : 0.f;
        #pragma unroll
        for (int d = 4; d > 0; d >>= 1) {
            ss += __shfl_xor_sync(0xffffffffu, ss, d);
            qq += __shfl_xor_sync(0xffffffffu, qq, d);
        }
        if (lane == 0) {
            float m = ss * (1.0f/Cd);
            float var = qq * (1.0f/Cd) - m*m;
            sbuf[16] = m;
            sbuf[17] = rsqrtf(var + EPSf);
        }
    }
    __syncthreads();
    mu = sbuf[16]; rstd = sbuf[17];
}

// ---------------- fused LN of img / img_warp / img_warp+mask ----------------
__global__ void ln3_kernel(const float* __restrict__ img,
                           const float* __restrict__ imw,
                           const float* __restrict__ msk,
                           const float* __restrict__ g1,
                           const float* __restrict__ b1) {
    int tok = blockIdx.x;
    int c   = threadIdx.x;
    int b   = tok / HW, pos = tok % HW;
    int off = (b*Cd + c)*HW + pos;

    float x0 = img[off];
    float x1 = imw[off];
    float x2 = x1 + msk[off];
    float gg = g1[c], bb = b1[c];

    __shared__ float sbuf[18];
    float mu, rs;

    block_meanvar(x0, sbuf, mu, rs);
    g_qln[tok*Cd + c] = (x0 - mu) * rs * gg + bb;
    __syncthreads();
    block_meanvar(x1, sbuf, mu, rs);
    g_kln[tok*Cd + c] = (x1 - mu) * rs * gg + bb;
    __syncthreads();
    block_meanvar(x2, sbuf, mu, rs);
    g_vln[tok*Cd + c] = (x2 - mu) * rs * gg + bb;
}

__global__ void ln_tok_kernel(const float* __restrict__ g1,
                              const float* __restrict__ b1) {
    int tok = blockIdx.x;
    int c   = threadIdx.x;
    float v = g_x1[tok*Cd + c];
    __shared__ float sbuf[18];
    float mu, rs;
    block_meanvar(v, sbuf, mu, rs);
    g_ln2[tok*Cd + c] = (v - mu) * rs * g1[c] + b1[c];
}

// ---------------- tf32 tensor-core GEMM, cp.async double buffered ----------
__device__ __forceinline__ unsigned f2tf32(float x) {
    unsigned r;
    asm("cvt.rna.tf32.f32 %0, %1;" : "=r"(r) : "f"(x));
    return r;
}
__device__ __forceinline__ void cp_async16(unsigned dst, const void* src) {
    asm volatile("cp.async.cg.shared.global [%0], [%1], 16;\n"
                 :: "r"(dst), "l"(src));
}
__device__ __forceinline__ void cp_commit() {
    asm volatile("cp.async.commit_group;\n");
}

// mode 0: C[m*N+n] = v
// mode 1: C[m*N+n] = v + res[(b*Cd+n)*HW+pos]
// mode 2: out[(b*Cd+n)*HW+pos] = v + res[m*N+n]
__device__ __forceinline__ void mma_body(const float* __restrict__ A,
                                         const float* __restrict__ Wt,
                                         const float* __restrict__ bias,
                                         float* __restrict__ C,
                                         int N, int K, int m0, int n0,
                                         int mode, const float* __restrict__ res) {
    extern __shared__ float smem[];
    float* As = smem;                 // [2][BM][KP]
    float* Ws = smem + 2*BM*KP;       // [2][BN][KP]

    int tid  = threadIdx.x;
    int lane = tid & 31, warp = tid >> 5;
    int wm = (warp >> 1) * 32, wn = (warp & 1) * 32;
    int g = lane >> 2, t4 = lane & 3;

    float acc[2][4][4] = {};
    int steps = K / BK;

    unsigned sA = (unsigned)__cvta_generic_to_shared(As);
    unsigned sW = (unsigned)__cvta_generic_to_shared(Ws);

    // stage load macro-ish lambda
    auto load_stage = [&](int kc, int s) {
        int k0 = kc * BK;
        // A: BM*BK floats = 1024 x 16B; 256 thr -> 4 each
        #pragma unroll
        for (int it = 0; it < 4; it++) {
            int idx = tid + it*256;
            int row = idx >> 3, ch = (idx & 7) * 4;
            cp_async16(sA + (unsigned)(((s*BM + row)*KP + ch) * 4),
                       &A[(size_t)(m0+row)*K + k0 + ch]);
        }
        // W: BN*BK floats = 512 x 16B; 2 each
        #pragma unroll
        for (int it = 0; it < 2; it++) {
            int idx = tid + it*256;
            int row = idx >> 3, ch = (idx & 7) * 4;
            cp_async16(sW + (unsigned)(((s*BN + row)*KP + ch) * 4),
                       &Wt[(size_t)(n0+row)*K + k0 + ch]);
        }
        cp_commit();
    };

    load_stage(0, 0);

    for (int kc = 0; kc < steps; kc++) {
        int s = kc & 1;
        if (kc + 1 < steps) {
            load_stage(kc + 1, (kc + 1) & 1);
            asm volatile("cp.async.wait_group 1;\n");
        } else {
            asm volatile("cp.async.wait_group 0;\n");
        }
        __syncthreads();

        float* Ab = As + s*BM*KP;
        float* Wb = Ws + s*BN*KP;
        #pragma unroll
        for (int ks = 0; ks < BK; ks += 8) {
            unsigned a[2][4], bf[4][2];
            #pragma unroll
            for (int mt = 0; mt < 2; mt++) {
                int rb = wm + mt*16;
                a[mt][0] = f2tf32(Ab[(rb + g    )*KP + ks + t4    ]);
                a[mt][1] = f2tf32(Ab[(rb + g + 8)*KP + ks + t4    ]);
                a[mt][2] = f2tf32(Ab[(rb + g    )*KP + ks + t4 + 4]);
                a[mt][3] = f2tf32(Ab[(rb + g + 8)*KP + ks + t4 + 4]);
            }
            #pragma unroll
            for (int nt = 0; nt < 4; nt++) {
                int nb = wn + nt*8 + g;
                bf[nt][0] = f2tf32(Wb[nb*KP + ks + t4    ]);
                bf[nt][1] = f2tf32(Wb[nb*KP + ks + t4 + 4]);
            }
            #pragma unroll
            for (int mt = 0; mt < 2; mt++)
                #pragma unroll
                for (int nt = 0; nt < 4; nt++)
                    asm volatile(
                        "mma.sync.aligned.m16n8k8.row.col.f32.tf32.tf32.f32 "
                        "{%0,%1,%2,%3}, {%4,%5,%6,%7}, {%8,%9}, {%0,%1,%2,%3};"
                        : "+f"(acc[mt][nt][0]), "+f"(acc[mt][nt][1]),
                          "+f"(acc[mt][nt][2]), "+f"(acc[mt][nt][3])
                        : "r"(a[mt][0]), "r"(a[mt][1]),
                          "r"(a[mt][2]), "r"(a[mt][3]),
                          "r"(bf[nt][0]), "r"(bf[nt][1]));
        }
        __syncthreads();
    }

    #pragma unroll
    for (int mt = 0; mt < 2; mt++) {
        #pragma unroll
        for (int nt = 0; nt < 4; nt++) {
            #pragma unroll
            for (int i = 0; i < 4; i++) {
                int mrow = m0 + wm + mt*16 + g + ((i >= 2) ? 8 : 0);
                int ncol = n0 + wn + nt*8 + 2*t4 + (i & 1);
                float v = acc[mt][nt][i] + bias[ncol];
                if (mode == 0) {
                    C[(size_t)mrow*N + ncol] = v;
                } else if (mode == 1) {
                    int b = mrow / HW, pos = mrow % HW;
                    C[(size_t)mrow*N + ncol] =
                        v + res[(size_t)(b*Cd + ncol)*HW + pos];
                } else {
                    int b = mrow / HW, pos = mrow % HW;
                    C[(size_t)(b*Cd + ncol)*HW + pos] =
                        v + res[(size_t)mrow*N + ncol];
                }
            }
        }
    }
}

__global__ void mma_gemm_kernel(const float* __restrict__ A,
                                const float* __restrict__ Wt,
                                const float* __restrict__ bias,
                                float* __restrict__ C,
                                int N, int K, int mode,
                                const float* __restrict__ res) {
    mma_body(A, Wt, bias, C, N, K, blockIdx.y*BM, blockIdx.x*BN, mode, res);
}

struct QKVArgs {
    const float* A[3];
    const float* W[3];
    const float* bias[3];
    float* C[3];
};
__global__ void mma_qkv_kernel(QKVArgs args) {
    int z = blockIdx.z;
    mma_body(args.A[z], args.W[z], args.bias[z], args.C[z],
             Cd, Cd, blockIdx.y*BM, blockIdx.x*BN, 0, nullptr);
}

// ---------------- tiled local attention ----------------
__global__ void attn_tile_kernel(const float* __restrict__ Wrel,
                                 const float* __restrict__ brel) {
    extern __shared__ float smem[];
    float* sK   = smem;
    float* sW   = sK + 32*KPAD;
    float* sS   = sW + 32*WPAD;
    float* sInv = sS + 16*SPAD;

    int tile = blockIdx.x;
    int h = blockIdx.y, b = blockIdx.z;
    int ty0 = (tile / (Wd/QT)) * QT;
    int tx0 = (tile % (Wd/QT)) * QT;
    int t = threadIdx.x;

    for (int i = t; i < W2Sd*32; i += 256) {
        int o = i >> 5, c = i & 31;
        sW[c*WPAD + o] = Wrel[(h*W2Sd + o)*HDd + c];
    }
    int wy0 = ty0 - MDd, wx0 = tx0 - MDd;
    for (int i = t; i < EXT2*32; i += 256) {
        int pos = i >> 5, c = i & 31;
        int wy = pos / EXT, wx = pos - (pos/EXT)*EXT;
        int ky = wy0 + wy, kx = wx0 + wx;
        float v = 0.f;
        if (ky >= 0 && ky < Hh && kx >= 0 && kx < Wd)
            v = g_K[(size_t)(b*HW + ky*Wd + kx)*Cd + h*HDd + c];
        sK[c*KPAD + pos] = v;
    }

    int q  = t >> 4;
    int lo = t & 15;
    int qy = q >> 2, qx = q & 3;
    int ty = ty0 + qy, tx = tx0 + qx;
    int tok = b*HW + ty*Wd + tx;
    float qreg[32];
    {
        const float* qp = g_Q + (size_t)tok*Cd + h*HDd;
        #pragma unroll
        for (int c = 0; c < 32; c++) qreg[c] = qp[c];
    }
    __syncthreads();

    const float scale = 0.17677669529663687f;
    for (int o = lo; o < W2Sd; o += 16) {
        int oy = o / WSd, ox = o - (o/WSd)*WSd;
        int ky = ty + oy - MDd, kx = tx + ox - MDd;
        float s = NEGINF;
        if (ky >= 0 && ky < Hh && kx >= 0 && kx < Wd) {
            int pos = (qy + oy)*EXT + (qx + ox);
            float d = 0.f, r = 0.f;
            #pragma unroll
            for (int c = 0; c < 32; c++) {
                d += qreg[c] * sK[c*KPAD + pos];
                r += qreg[c] * sW[c*WPAD + o];
            }
            s = d*scale + r + brel[h*W2Sd + o];
        }
        sS[q*SPAD + o] = s;
    }
    __syncthreads();

    {
        float mx = NEGINF;
        for (int o = lo; o < W2Sd; o += 16)
            mx = fmaxf(mx, sS[q*SPAD + o]);
        #pragma unroll
        for (int d = 8; d > 0; d >>= 1)
            mx = fmaxf(mx, __shfl_xor_sync(0xffffffffu, mx, d));
        float sum = 0.f;
        for (int o = lo; o < W2Sd; o += 16) {
            float s = sS[q*SPAD + o];
            float e = (s > -1e37f) ? __expf(s - mx) : 0.f;
            sS[q*SPAD + o] = e;
            sum += e;
        }
        #pragma unroll
        for (int d = 8; d > 0; d >>= 1)
            sum += __shfl_xor_sync(0xffffffffu, sum, d);
        if (lo == 0) sInv[q] = 1.f / sum;
    }
    __syncthreads();

    for (int i = t; i < EXT2*32; i += 256) {
        int pos = i >> 5, c = i & 31;
        int wy = pos / EXT, wx = pos - (pos/EXT)*EXT;
        int ky = wy0 + wy, kx = wx0 + wx;
        float v = 0.f;
        if (ky >= 0 && ky < Hh && kx >= 0 && kx < Wd)
            v = g_V[(size_t)(b*HW + ky*Wd + kx)*Cd + h*HDd + c];
        sK[c*KPAD + pos] = v;
    }
    __syncthreads();

    int c = t & 31, q8 = t >> 5;
    #pragma unroll
    for (int rep = 0; rep < 2; rep++) {
        int qq = q8 + rep*8;
        int qqy = qq >> 2, qqx = qq & 3;
        float acc = 0.f;
        #pragma unroll
        for (int oy = 0; oy < WSd; oy++) {
            int rowbase = (qqy + oy)*EXT + qqx;
            int srow = qq*SPAD + oy*WSd;
            #pragma unroll
            for (int ox = 0; ox < WSd; ox++)
                acc += sS[srow + ox] * sK[c*KPAD + rowbase + ox];
        }
        int tok2 = b*HW + (ty0 + qqy)*Wd + (tx0 + qqx);
        g_att[(size_t)tok2*Cd + h*HDd + c] = acc * sInv[qq];
    }
}

// ---------------- GroupNorm stats per (b, group) ----------------
__global__ void gn_stats_kernel() {
    int bg = blockIdx.x;
    int b = bg / GNg, g = bg % GNg;
    int tid = threadIdx.x;
    float sm = 0.f, sq = 0.f;
    for (int i = tid; i < HW*32; i += 256) {
        int ch  = g*32 + (i & 31);
        int pos = i >> 5;
        float v = g_h1[(size_t)(b*HW + pos)*HIDd + ch];
        sm += v; sq += v*v;
    }
    #pragma unroll
    for (int d = 16; d > 0; d >>= 1) {
        sm += __shfl_xor_sync(0xffffffffu, sm, d);
        sq += __shfl_xor_sync(0xffffffffu, sq, d);
    }
    __shared__ float s1[8], s2[8];
    int warp = tid >> 5, lane = tid & 31;
    if (lane == 0) { s1[warp] = sm; s2[warp] = sq; }
    __syncthreads();
    if (tid == 0) {
        float ss = 0.f, qq = 0.f;
        #pragma unroll
        for (int i = 0; i < 8; i++) { ss += s1[i]; qq += s2[i]; }
        float cnt = (float)(HW*32);
        float mu  = ss / cnt;
        float var = qq / cnt - mu*mu;
        g_gnm[bg*2]   = mu;
        g_gnm[bg*2+1] = rsqrtf(var + EPSf);
    }
}

// ---------------- fused GN + GELU + 5x5 depthwise conv ----------------
// grid (25 spatial tiles, 16 ch-groups, B); block 256; 8x8 out tile, 64 ch
__global__ void dwconv_fused_kernel(const float* __restrict__ gg,
                                    const float* __restrict__ gb,
                                    const float* __restrict__ Wdw) {
    __shared__ float sT[144][68];   // 12x12 halo x 64 ch (+pad)

    int tileid = blockIdx.x;
    int cg = blockIdx.y, b = blockIdx.z;
    int ty0 = (tileid / 5) * 8, tx0 = (tileid % 5) * 8;
    int tid = threadIdx.x;
    int ch  = tid & 63;
    int chg = cg*64 + ch;

    float gamma = gg[chg], beta = gb[chg];
    int grp = chg >> 5;
    float mu = g_gnm[(b*GNg + grp)*2];
    float rs = g_gnm[(b*GNg + grp)*2 + 1];

    float wreg[25];
    #pragma unroll
    for (int i = 0; i < 25; i++) wreg[i] = Wdw[chg*25 + i];

    // load 12x12x64 input tile, apply GN+GELU inline
    for (int i = tid; i < 144*64; i += 256) {
        int pos = i >> 6;
        int wy = pos / 12, wx = pos - (pos/12)*12;
        int y = ty0 + wy - 2, x = tx0 + wx - 2;
        float v = 0.f;
        if (y >= 0 && y < Hh && x >= 0 && x < Wd) {
            float hv = g_h1[(size_t)(b*HW + y*Wd + x)*HIDd + chg];
            hv = (hv - mu) * rs * gamma + beta;
            v = 0.5f * hv * (1.f + erff(hv * 0.70710678118654752f));
        }
        sT[pos][ch] = v;
    }
    __syncthreads();

    int pg = tid >> 6;   // 0..3, each handles 16 of 64 positions
    #pragma unroll
    for (int p = 0; p < 16; p++) {
        int po = pg*16 + p;
        int y = po >> 3, x = po & 7;
        float acc = 0.f;
        #pragma unroll
        for (int dy = 0; dy < 5; dy++)
            #pragma unroll
            for (int dx = 0; dx < 5; dx++)
                acc += wreg[dy*5+dx] * sT[(y+dy)*12 + (x+dx)][ch];
        g_cv[(size_t)(b*HW + (ty0+y)*Wd + (tx0+x))*HIDd + chg] = acc;
    }
}

// ---------------- launch ----------------
extern "C" void kernel_launch(void* const* d_in, const int* in_sizes, int n_in,
                              void* d_out, int out_size) {
    const float* img   = (const float*)d_in[0];
    const float* imw   = (const float*)d_in[1];
    const float* msk   = (const float*)d_in[2];
    const float* ln1g  = (const float*)d_in[3];
    const float* ln1b  = (const float*)d_in[4];
    const float* ln2g  = (const float*)d_in[5];
    const float* ln2b  = (const float*)d_in[6];
    const float* Wq    = (const float*)d_in[7];
    const float* bq    = (const float*)d_in[8];
    const float* Wk    = (const float*)d_in[9];
    const float* bk    = (const float*)d_in[10];
    const float* Wv    = (const float*)d_in[11];
    const float* bv    = (const float*)d_in[12];
    const float* Wrel  = (const float*)d_in[13];
    const float* brel  = (const float*)d_in[14];
    const float* Wproj = (const float*)d_in[15];
    const float* bproj = (const float*)d_in[16];
    const float* W1    = (const float*)d_in[17];
    const float* bW1   = (const float*)d_in[18];
    const float* gng   = (const float*)d_in[19];
    const float* gnb   = (const float*)d_in[20];
    const float* Wdw   = (const float*)d_in[21];
    const float* W2    = (const float*)d_in[22];
    const float* bW2   = (const float*)d_in[23];
    float* out = (float*)d_out;

    float *qln, *kln, *vln, *Q, *K, *V, *att, *x1, *ln2, *h1, *cv;
    cudaGetSymbolAddress((void**)&qln, g_qln);
    cudaGetSymbolAddress((void**)&kln, g_kln);
    cudaGetSymbolAddress((void**)&vln, g_vln);
    cudaGetSymbolAddress((void**)&Q,   g_Q);
    cudaGetSymbolAddress((void**)&K,   g_K);
    cudaGetSymbolAddress((void**)&V,   g_V);
    cudaGetSymbolAddress((void**)&att, g_att);
    cudaGetSymbolAddress((void**)&x1,  g_x1);
    cudaGetSymbolAddress((void**)&ln2, g_ln2);
    cudaGetSymbolAddress((void**)&h1,  g_h1);
    cudaGetSymbolAddress((void**)&cv,  g_cv);

    int gemm_smem = (2*BM*KP + 2*BN*KP) * sizeof(float);   // 55296
    cudaFuncSetAttribute(mma_gemm_kernel,
                         cudaFuncAttributeMaxDynamicSharedMemorySize, gemm_smem);
    cudaFuncSetAttribute(mma_qkv_kernel,
                         cudaFuncAttributeMaxDynamicSharedMemorySize, gemm_smem);

    // 1. LayerNorms of q/k/v sources
    ln3_kernel<<<TOK, 256>>>(img, imw, msk, ln1g, ln1b);

    // 2. QKV projections
    QKVArgs qa;
    qa.A[0] = qln; qa.A[1] = kln; qa.A[2] = vln;
    qa.W[0] = Wq;  qa.W[1] = Wk;  qa.W[2] = Wv;
    qa.bias[0] = bq; qa.bias[1] = bk; qa.bias[2] = bv;
    qa.C[0] = Q; qa.C[1] = K; qa.C[2] = V;
    mma_qkv_kernel<<<dim3(Cd/BN, TOK/BM, 3), 256, gemm_smem>>>(qa);

    // 3. tiled windowed attention
    int attn_smem = (32*KPAD + 32*WPAD + 16*SPAD + 16) * sizeof(float);
    cudaFuncSetAttribute(attn_tile_kernel,
                         cudaFuncAttributeMaxDynamicSharedMemorySize, attn_smem);
    attn_tile_kernel<<<dim3((Hh/QT)*(Wd/QT), NHd, Bz), 256, attn_smem>>>(Wrel, brel);

    // 4. output projection + fused residual -> x1
    mma_gemm_kernel<<<dim3(Cd/BN, TOK/BM), 256, gemm_smem>>>(att, Wproj, bproj, x1,
                                                             Cd, Cd, 1, img);

    // 5. MLP branch
    ln_tok_kernel<<<TOK, 256>>>(ln2g, ln2b);
    mma_gemm_kernel<<<dim3(HIDd/BN, TOK/BM), 256, gemm_smem>>>(ln2, W1, bW1, h1,
                                                               HIDd, Cd, 0, nullptr);
    gn_stats_kernel<<<Bz*GNg, 256>>>();
    dwconv_fused_kernel<<<dim3(25, HIDd/64, Bz), 256>>>(gng, gnb, Wdw);

    // 6. W2 + fused final residual + transpose to BCHW
    mma_gemm_kernel<<<dim3(Cd/BN, TOK/BM), 256, gemm_smem>>>(cv, W2, bW2, out,
                                                             Cd, HIDd, 2, x1);
}

// round 5
// speedup vs baseline: 5.5994x; 1.0017x over previous
#include <cuda_runtime.h>
#include <math.h>

#define Bz   2
#define Cd   256
#define Hh   40
#define Wd   40
#define HW   1600
#define TOK  3200
#define NHd  8
#define HDd  32
#define WSd  15
#define W2Sd 225
#define NPAD 256           // padded rel width
#define MDd  7
#define HIDd 1024
#define GNg  32
#define EPSf 1e-5f
#define NEGINF -1e38f

// attention tiling
#define QT   4
#define EXT  18
#define EXT2 (EXT*EXT)
#define KPAD 325
#define SPAD 228

// GEMM tiling
#define BN 64
#define BK 32
#define KP 36

// ---------------- scratch ----------------
__device__ float g_qln[TOK*Cd];
__device__ float g_kln[TOK*Cd];
__device__ float g_vln[TOK*Cd];
__device__ float g_Q[TOK*Cd];
__device__ float g_K[TOK*Cd];
__device__ float g_V[TOK*Cd];
__device__ float g_att[TOK*Cd];
__device__ float g_x1[TOK*Cd];
__device__ float g_ln2[TOK*Cd];
__device__ float g_h1[TOK*HIDd];
__device__ float g_cv[TOK*HIDd];
__device__ float g_gnm[Bz*GNg*2];
__device__ float g_rel[NHd*TOK*NPAD];     // q-conditioned rel bias, padded
__device__ float g_wrelp[NHd*NPAD*HDd];   // padded Wrel
__device__ float g_brelp[NHd*NPAD];       // padded brel

// ---------------- block mean/var helper (256 threads) ----------------
__device__ __forceinline__ void block_meanvar(float v, float* sbuf,
                                              float& mu, float& rstd) {
    float s = v, q = v*v;
    #pragma unroll
    for (int d = 16; d > 0; d >>= 1) {
        s += __shfl_xor_sync(0xffffffffu, s, d);
        q += __shfl_xor_sync(0xffffffffu, q, d);
    }
    int warp = threadIdx.x >> 5, lane = threadIdx.x & 31;
    if (lane == 0) { sbuf[warp] = s; sbuf[8 + warp] = q; }
    __syncthreads();
    if (warp == 0) {
        float ss = (lane < 8) ? sbuf[lane] : 0.f;
        float qq = (lane < 8) ? sbuf[8 + lane] : 0.f;
        #pragma unroll
        for (int d = 4; d > 0; d >>= 1) {
            ss += __shfl_xor_sync(0xffffffffu, ss, d);
            qq += __shfl_xor_sync(0xffffffffu, qq, d);
        }
        if (lane == 0) {
            float m = ss * (1.0f/Cd);
            float var = qq * (1.0f/Cd) - m*m;
            sbuf[16] = m;
            sbuf[17] = rsqrtf(var + EPSf);
        }
    }
    __syncthreads();
    mu = sbuf[16]; rstd = sbuf[17];
}

// ---------------- fused LN of img / img_warp / img_warp+mask ----------------
__global__ void ln3_kernel(const float* __restrict__ img,
                           const float* __restrict__ imw,
                           const float* __restrict__ msk,
                           const float* __restrict__ g1,
                           const float* __restrict__ b1) {
    int tok = blockIdx.x;
    int c   = threadIdx.x;
    int b   = tok / HW, pos = tok % HW;
    int off = (b*Cd + c)*HW + pos;

    float x0 = img[off];
    float x1 = imw[off];
    float x2 = x1 + msk[off];
    float gg = g1[c], bb = b1[c];

    __shared__ float sbuf[18];
    float mu, rs;

    block_meanvar(x0, sbuf, mu, rs);
    g_qln[tok*Cd + c] = (x0 - mu) * rs * gg + bb;
    __syncthreads();
    block_meanvar(x1, sbuf, mu, rs);
    g_kln[tok*Cd + c] = (x1 - mu) * rs * gg + bb;
    __syncthreads();
    block_meanvar(x2, sbuf, mu, rs);
    g_vln[tok*Cd + c] = (x2 - mu) * rs * gg + bb;
}

__global__ void ln_tok_kernel(const float* __restrict__ g1,
                              const float* __restrict__ b1) {
    int tok = blockIdx.x;
    int c   = threadIdx.x;
    float v = g_x1[tok*Cd + c];
    __shared__ float sbuf[18];
    float mu, rs;
    block_meanvar(v, sbuf, mu, rs);
    g_ln2[tok*Cd + c] = (v - mu) * rs * g1[c] + b1[c];
}

// ---------------- pad Wrel/brel ----------------
__global__ void relprep_kernel(const float* __restrict__ Wrel,
                               const float* __restrict__ brel) {
    int idx = blockIdx.x*256 + threadIdx.x;          // over NH*NPAD
    if (idx < NHd*NPAD) {
        int h = idx / NPAD, n = idx % NPAD;
        g_brelp[idx] = (n < W2Sd) ? brel[h*W2Sd + n] : 0.f;
        #pragma unroll
        for (int c = 0; c < HDd; c++)
            g_wrelp[idx*HDd + c] = (n < W2Sd) ? Wrel[(h*W2Sd + n)*HDd + c] : 0.f;
    }
}

// ---------------- tf32 tensor-core GEMM, cp.async double buffered ----------
__device__ __forceinline__ unsigned f2tf32(float x) {
    unsigned r;
    asm("cvt.rna.tf32.f32 %0, %1;" : "=r"(r) : "f"(x));
    return r;
}
__device__ __forceinline__ void cp_async16(unsigned dst, const void* src) {
    asm volatile("cp.async.cg.shared.global [%0], [%1], 16;\n"
                 :: "r"(dst), "l"(src));
}
__device__ __forceinline__ void cp_commit() {
    asm volatile("cp.async.commit_group;\n");
}

// mode 0: C[m*N+n] = v
// mode 1: C[m*N+n] = v + res[(b*Cd+n)*HW+pos]
// mode 2: out[(b*Cd+n)*HW+pos] = v + res[m*N+n]
template<int BMT>
__device__ __forceinline__ void mma_body(const float* __restrict__ A, int lda,
                                         const float* __restrict__ Wt,
                                         const float* __restrict__ bias,
                                         float* __restrict__ C,
                                         int N, int K, int m0, int n0,
                                         int mode, const float* __restrict__ res) {
    constexpr int MT = BMT / 64;      // m16-tiles per warp
    extern __shared__ float smem[];
    float* As = smem;                  // [2][BMT][KP]
    float* Ws = smem + 2*BMT*KP;       // [2][BN][KP]

    int tid  = threadIdx.x;
    int lane = tid & 31, warp = tid >> 5;
    int wm = (warp >> 1) * (16*MT), wn = (warp & 1) * 32;
    int g = lane >> 2, t4 = lane & 3;

    float acc[MT][4][4] = {};
    int steps = K / BK;

    unsigned sA = (unsigned)__cvta_generic_to_shared(As);
    unsigned sW = (unsigned)__cvta_generic_to_shared(Ws);

    auto load_stage = [&](int kc, int s) {
        int k0 = kc * BK;
        #pragma unroll
        for (int it = 0; it < BMT/32; it++) {
            int idx = tid + it*256;
            int row = idx >> 3, ch = (idx & 7) * 4;
            cp_async16(sA + (unsigned)(((s*BMT + row)*KP + ch) * 4),
                       &A[(size_t)(m0+row)*lda + k0 + ch]);
        }
        #pragma unroll
        for (int it = 0; it < 2; it++) {
            int idx = tid + it*256;
            int row = idx >> 3, ch = (idx & 7) * 4;
            cp_async16(sW + (unsigned)(((s*BN + row)*KP + ch) * 4),
                       &Wt[(size_t)(n0+row)*K + k0 + ch]);
        }
        cp_commit();
    };

    load_stage(0, 0);

    for (int kc = 0; kc < steps; kc++) {
        int s = kc & 1;
        if (kc + 1 < steps) {
            load_stage(kc + 1, (kc + 1) & 1);
            asm volatile("cp.async.wait_group 1;\n");
        } else {
            asm volatile("cp.async.wait_group 0;\n");
        }
        __syncthreads();

        float* Ab = As + s*BMT*KP;
        float* Wb = Ws + s*BN*KP;
        #pragma unroll
        for (int ks = 0; ks < BK; ks += 8) {
            unsigned a[MT][4], bf[4][2];
            #pragma unroll
            for (int mt = 0; mt < MT; mt++) {
                int rb = wm + mt*16;
                a[mt][0] = f2tf32(Ab[(rb + g    )*KP + ks + t4    ]);
                a[mt][1] = f2tf32(Ab[(rb + g + 8)*KP + ks + t4    ]);
                a[mt][2] = f2tf32(Ab[(rb + g    )*KP + ks + t4 + 4]);
                a[mt][3] = f2tf32(Ab[(rb + g + 8)*KP + ks + t4 + 4]);
            }
            #pragma unroll
            for (int nt = 0; nt < 4; nt++) {
                int nb = wn + nt*8 + g;
                bf[nt][0] = f2tf32(Wb[nb*KP + ks + t4    ]);
                bf[nt][1] = f2tf32(Wb[nb*KP + ks + t4 + 4]);
            }
            #pragma unroll
            for (int mt = 0; mt < MT; mt++)
                #pragma unroll
                for (int nt = 0; nt < 4; nt++)
                    asm volatile(
                        "mma.sync.aligned.m16n8k8.row.col.f32.tf32.tf32.f32 "
                        "{%0,%1,%2,%3}, {%4,%5,%6,%7}, {%8,%9}, {%0,%1,%2,%3};"
                        : "+f"(acc[mt][nt][0]), "+f"(acc[mt][nt][1]),
                          "+f"(acc[mt][nt][2]), "+f"(acc[mt][nt][3])
                        : "r"(a[mt][0]), "r"(a[mt][1]),
                          "r"(a[mt][2]), "r"(a[mt][3]),
                          "r"(bf[nt][0]), "r"(bf[nt][1]));
        }
        __syncthreads();
    }

    #pragma unroll
    for (int mt = 0; mt < MT; mt++) {
        #pragma unroll
        for (int nt = 0; nt < 4; nt++) {
            #pragma unroll
            for (int i = 0; i < 4; i++) {
                int mrow = m0 + wm + mt*16 + g + ((i >= 2) ? 8 : 0);
                int ncol = n0 + wn + nt*8 + 2*t4 + (i & 1);
                float v = acc[mt][nt][i] + bias[ncol];
                if (mode == 0) {
                    C[(size_t)mrow*N + ncol] = v;
                } else if (mode == 1) {
                    int b = mrow / HW, pos = mrow % HW;
                    C[(size_t)mrow*N + ncol] =
                        v + res[(size_t)(b*Cd + ncol)*HW + pos];
                } else {
                    int b = mrow / HW, pos = mrow % HW;
                    C[(size_t)(b*Cd + ncol)*HW + pos] =
                        v + res[(size_t)mrow*N + ncol];
                }
            }
        }
    }
}

template<int BMT>
__global__ void mma_gemm_kernel(const float* __restrict__ A,
                                const float* __restrict__ Wt,
                                const float* __restrict__ bias,
                                float* __restrict__ C,
                                int N, int K, int mode,
                                const float* __restrict__ res) {
    mma_body<BMT>(A, K, Wt, bias, C, N, K, blockIdx.y*BMT, blockIdx.x*BN, mode, res);
}

struct QKVArgs {
    const float* A[3];
    const float* W[3];
    const float* bias[3];
    float* C[3];
};
__global__ void mma_qkv_kernel(QKVArgs args) {
    int z = blockIdx.z;
    mma_body<128>(args.A[z], Cd, args.W[z], args.bias[z], args.C[z],
                  Cd, Cd, blockIdx.y*128, blockIdx.x*BN, 0, nullptr);
}

// rel GEMM: per head z, rel[z][tok][n] = Q[tok, z*32..] x Wrelp[z]^T + brelp[z]
__global__ void mma_rel_kernel() {
    int z = blockIdx.z;
    mma_body<128>(g_Q + z*HDd, Cd,
                  g_wrelp + (size_t)z*NPAD*HDd,
                  g_brelp + z*NPAD,
                  g_rel + (size_t)z*TOK*NPAD,
                  NPAD, HDd, blockIdx.y*128, blockIdx.x*BN, 0, nullptr);
}

// ---------------- tiled local attention ----------------
__global__ void attn_tile_kernel() {
    extern __shared__ float smem[];
    float* sK   = smem;                 // [32][KPAD]
    float* sS   = sK + 32*KPAD;         // [16][SPAD]
    float* sInv = sS + 16*SPAD;

    int tile = blockIdx.x;
    int h = blockIdx.y, b = blockIdx.z;
    int ty0 = (tile / (Wd/QT)) * QT;
    int tx0 = (tile % (Wd/QT)) * QT;
    int t = threadIdx.x;

    int wy0 = ty0 - MDd, wx0 = tx0 - MDd;
    for (int i = t; i < EXT2*32; i += 256) {
        int pos = i >> 5, c = i & 31;
        int wy = pos / EXT, wx = pos - (pos/EXT)*EXT;
        int ky = wy0 + wy, kx = wx0 + wx;
        float v = 0.f;
        if (ky >= 0 && ky < Hh && kx >= 0 && kx < Wd)
            v = g_K[(size_t)(b*HW + ky*Wd + kx)*Cd + h*HDd + c];
        sK[c*KPAD + pos] = v;
    }

    int q  = t >> 4;
    int lo = t & 15;
    int qy = q >> 2, qx = q & 3;
    int ty = ty0 + qy, tx = tx0 + qx;
    int tok = b*HW + ty*Wd + tx;
    float qreg[32];
    {
        const float* qp = g_Q + (size_t)tok*Cd + h*HDd;
        #pragma unroll
        for (int c = 0; c < 32; c++) qreg[c] = qp[c];
    }
    __syncthreads();

    const float scale = 0.17677669529663687f;
    const float* relp = g_rel + (size_t)(h*TOK + tok)*NPAD;
    for (int o = lo; o < W2Sd; o += 16) {
        int oy = o / WSd, ox = o - (o/WSd)*WSd;
        int ky = ty + oy - MDd, kx = tx + ox - MDd;
        float s = NEGINF;
        if (ky >= 0 && ky < Hh && kx >= 0 && kx < Wd) {
            int pos = (qy + oy)*EXT + (qx + ox);
            float d = 0.f;
            #pragma unroll
            for (int c = 0; c < 32; c++)
                d += qreg[c] * sK[c*KPAD + pos];
            s = d*scale + relp[o];
        }
        sS[q*SPAD + o] = s;
    }
    __syncthreads();

    {
        float mx = NEGINF;
        for (int o = lo; o < W2Sd; o += 16)
            mx = fmaxf(mx, sS[q*SPAD + o]);
        #pragma unroll
        for (int d = 8; d > 0; d >>= 1)
            mx = fmaxf(mx, __shfl_xor_sync(0xffffffffu, mx, d));
        float sum = 0.f;
        for (int o = lo; o < W2Sd; o += 16) {
            float s = sS[q*SPAD + o];
            float e = (s > -1e37f) ? __expf(s - mx) : 0.f;
            sS[q*SPAD + o] = e;
            sum += e;
        }
        #pragma unroll
        for (int d = 8; d > 0; d >>= 1)
            sum += __shfl_xor_sync(0xffffffffu, sum, d);
        if (lo == 0) sInv[q] = 1.f / sum;
    }
    __syncthreads();

    for (int i = t; i < EXT2*32; i += 256) {
        int pos = i >> 5, c = i & 31;
        int wy = pos / EXT, wx = pos - (pos/EXT)*EXT;
        int ky = wy0 + wy, kx = wx0 + wx;
        float v = 0.f;
        if (ky >= 0 && ky < Hh && kx >= 0 && kx < Wd)
            v = g_V[(size_t)(b*HW + ky*Wd + kx)*Cd + h*HDd + c];
        sK[c*KPAD + pos] = v;
    }
    __syncthreads();

    int c = t & 31, q8 = t >> 5;
    #pragma unroll
    for (int rep = 0; rep < 2; rep++) {
        int qq = q8 + rep*8;
        int qqy = qq >> 2, qqx = qq & 3;
        float acc = 0.f;
        #pragma unroll
        for (int oy = 0; oy < WSd; oy++) {
            int rowbase = (qqy + oy)*EXT + qqx;
            int srow = qq*SPAD + oy*WSd;
            #pragma unroll
            for (int ox = 0; ox < WSd; ox++)
                acc += sS[srow + ox] * sK[c*KPAD + rowbase + ox];
        }
        int tok2 = b*HW + (ty0 + qqy)*Wd + (tx0 + qqx);
        g_att[(size_t)tok2*Cd + h*HDd + c] = acc * sInv[qq];
    }
}

// ---------------- GroupNorm stats per (b, group) ----------------
__global__ void gn_stats_kernel() {
    int bg = blockIdx.x;
    int b = bg / GNg, g = bg % GNg;
    int tid = threadIdx.x;
    float sm = 0.f, sq = 0.f;
    for (int i = tid; i < HW*32; i += 256) {
        int ch  = g*32 + (i & 31);
        int pos = i >> 5;
        float v = g_h1[(size_t)(b*HW + pos)*HIDd + ch];
        sm += v; sq += v*v;
    }
    #pragma unroll
    for (int d = 16; d > 0; d >>= 1) {
        sm += __shfl_xor_sync(0xffffffffu, sm, d);
        sq += __shfl_xor_sync(0xffffffffu, sq, d);
    }
    __shared__ float s1[8], s2[8];
    int warp = tid >> 5, lane = tid & 31;
    if (lane == 0) { s1[warp] = sm; s2[warp] = sq; }
    __syncthreads();
    if (tid == 0) {
        float ss = 0.f, qq = 0.f;
        #pragma unroll
        for (int i = 0; i < 8; i++) { ss += s1[i]; qq += s2[i]; }
        float cnt = (float)(HW*32);
        float mu  = ss / cnt;
        float var = qq / cnt - mu*mu;
        g_gnm[bg*2]   = mu;
        g_gnm[bg*2+1] = rsqrtf(var + EPSf);
    }
}

// ---------------- fused GN + GELU + 5x5 depthwise conv ----------------
__global__ void dwconv_fused_kernel(const float* __restrict__ gg,
                                    const float* __restrict__ gb,
                                    const float* __restrict__ Wdw) {
    __shared__ float sT[144][68];

    int tileid = blockIdx.x;
    int cg = blockIdx.y, b = blockIdx.z;
    int ty0 = (tileid / 5) * 8, tx0 = (tileid % 5) * 8;
    int tid = threadIdx.x;
    int ch  = tid & 63;
    int chg = cg*64 + ch;

    float gamma = gg[chg], beta = gb[chg];
    int grp = chg >> 5;
    float mu = g_gnm[(b*GNg + grp)*2];
    float rs = g_gnm[(b*GNg + grp)*2 + 1];

    float wreg[25];
    #pragma unroll
    for (int i = 0; i < 25; i++) wreg[i] = Wdw[chg*25 + i];

    for (int i = tid; i < 144*64; i += 256) {
        int pos = i >> 6;
        int wy = pos / 12, wx = pos - (pos/12)*12;
        int y = ty0 + wy - 2, x = tx0 + wx - 2;
        float v = 0.f;
        if (y >= 0 && y < Hh && x >= 0 && x < Wd) {
            float hv = g_h1[(size_t)(b*HW + y*Wd + x)*HIDd + chg];
            hv = (hv - mu) * rs * gamma + beta;
            v = 0.5f * hv * (1.f + erff(hv * 0.70710678118654752f));
        }
        sT[pos][ch] = v;
    }
    __syncthreads();

    int pg = tid >> 6;
    #pragma unroll
    for (int p = 0; p < 16; p++) {
        int po = pg*16 + p;
        int y = po >> 3, x = po & 7;
        float acc = 0.f;
        #pragma unroll
        for (int dy = 0; dy < 5; dy++)
            #pragma unroll
            for (int dx = 0; dx < 5; dx++)
                acc += wreg[dy*5+dx] * sT[(y+dy)*12 + (x+dx)][ch];
        g_cv[(size_t)(b*HW + (ty0+y)*Wd + (tx0+x))*HIDd + chg] = acc;
    }
}

// ---------------- launch ----------------
extern "C" void kernel_launch(void* const* d_in, const int* in_sizes, int n_in,
                              void* d_out, int out_size) {
    const float* img   = (const float*)d_in[0];
    const float* imw   = (const float*)d_in[1];
    const float* msk   = (const float*)d_in[2];
    const float* ln1g  = (const float*)d_in[3];
    const float* ln1b  = (const float*)d_in[4];
    const float* ln2g  = (const float*)d_in[5];
    const float* ln2b  = (const float*)d_in[6];
    const float* Wq    = (const float*)d_in[7];
    const float* bq    = (const float*)d_in[8];
    const float* Wk    = (const float*)d_in[9];
    const float* bk    = (const float*)d_in[10];
    const float* Wv    = (const float*)d_in[11];
    const float* bv    = (const float*)d_in[12];
    const float* Wrel  = (const float*)d_in[13];
    const float* brel  = (const float*)d_in[14];
    const float* Wproj = (const float*)d_in[15];
    const float* bproj = (const float*)d_in[16];
    const float* W1    = (const float*)d_in[17];
    const float* bW1   = (const float*)d_in[18];
    const float* gng   = (const float*)d_in[19];
    const float* gnb   = (const float*)d_in[20];
    const float* Wdw   = (const float*)d_in[21];
    const float* W2    = (const float*)d_in[22];
    const float* bW2   = (const float*)d_in[23];
    float* out = (float*)d_out;

    float *qln, *kln, *vln, *Q, *K, *V, *att, *x1, *ln2, *h1, *cv;
    cudaGetSymbolAddress((void**)&qln, g_qln);
    cudaGetSymbolAddress((void**)&kln, g_kln);
    cudaGetSymbolAddress((void**)&vln, g_vln);
    cudaGetSymbolAddress((void**)&Q,   g_Q);
    cudaGetSymbolAddress((void**)&K,   g_K);
    cudaGetSymbolAddress((void**)&V,   g_V);
    cudaGetSymbolAddress((void**)&att, g_att);
    cudaGetSymbolAddress((void**)&x1,  g_x1);
    cudaGetSymbolAddress((void**)&ln2, g_ln2);
    cudaGetSymbolAddress((void**)&h1,  g_h1);
    cudaGetSymbolAddress((void**)&cv,  g_cv);

    int smem128 = (2*128*KP + 2*BN*KP) * sizeof(float);  // 55296
    int smem64  = (2*64*KP  + 2*BN*KP) * sizeof(float);  // 36864
    cudaFuncSetAttribute(mma_gemm_kernel<128>,
                         cudaFuncAttributeMaxDynamicSharedMemorySize, smem128);
    cudaFuncSetAttribute(mma_gemm_kernel<64>,
                         cudaFuncAttributeMaxDynamicSharedMemorySize, smem64);
    cudaFuncSetAttribute(mma_qkv_kernel,
                         cudaFuncAttributeMaxDynamicSharedMemorySize, smem128);
    cudaFuncSetAttribute(mma_rel_kernel,
                         cudaFuncAttributeMaxDynamicSharedMemorySize, smem128);

    // 0. pad rel weights
    relprep_kernel<<<(NHd*NPAD + 255)/256, 256>>>(Wrel, brel);

    // 1. LayerNorms
    ln3_kernel<<<TOK, 256>>>(img, imw, msk, ln1g, ln1b);

    // 2. QKV projections
    QKVArgs qa;
    qa.A[0] = qln; qa.A[1] = kln; qa.A[2] = vln;
    qa.W[0] = Wq;  qa.W[1] = Wk;  qa.W[2] = Wv;
    qa.bias[0] = bq; qa.bias[1] = bk; qa.bias[2] = bv;
    qa.C[0] = Q; qa.C[1] = K; qa.C[2] = V;
    mma_qkv_kernel<<<dim3(Cd/BN, TOK/128, 3), 256, smem128>>>(qa);

    // 2b. rel bias GEMM (per head)
    mma_rel_kernel<<<dim3(NPAD/BN, TOK/128, NHd), 256, smem128>>>();

    // 3. tiled windowed attention
    int attn_smem = (32*KPAD + 16*SPAD + 16) * sizeof(float);
    cudaFuncSetAttribute(attn_tile_kernel,
                         cudaFuncAttributeMaxDynamicSharedMemorySize, attn_smem);
    attn_tile_kernel<<<dim3((Hh/QT)*(Wd/QT), NHd, Bz), 256, attn_smem>>>();

    // 4. output projection + fused residual -> x1  (BM=64, grid 200)
    mma_gemm_kernel<64><<<dim3(Cd/BN, TOK/64), 256, smem64>>>(att, Wproj, bproj, x1,
                                                              Cd, Cd, 1, img);

    // 5. MLP branch
    ln_tok_kernel<<<TOK, 256>>>(ln2g, ln2b);
    mma_gemm_kernel<128><<<dim3(HIDd/BN, TOK/128), 256, smem128>>>(ln2, W1, bW1, h1,
                                                                   HIDd, Cd, 0, nullptr);
    gn_stats_kernel<<<Bz*GNg, 256>>>();
    dwconv_fused_kernel<<<dim3(25, HIDd/64, Bz), 256>>>(gng, gnb, Wdw);

    // 6. W2 + fused final residual + transpose to BCHW  (BM=64, grid 200)
    mma_gemm_kernel<64><<<dim3(Cd/BN, TOK/64), 256, smem64>>>(cv, W2, bW2, out,
                                                              Cd, HIDd, 2, x1);
}